// round 9
// baseline (speedup 1.0000x reference)
#include <cuda_runtime.h>
#include <cuda_fp16.h>
#include <math.h>

// Problem constants (fixed for this dataset)
#define NN 50000
#define EE 800000
#define ET (EE + NN)      // 850000 edges incl. self loops
#define H1 4
#define C1 64
#define D1 256            // H1*C1
#define C2 64
#define IN1 128
#define NEG_SLOPE 0.2f

// ---------------- scratch (device globals, no runtime alloc) ----------------
__device__ __half2 g_h1h[(size_t)NN * D1 / 2];   // fp16 h1 (gather source)
__device__ float   g_acc1[(size_t)NN * D1];      // layer1 output (post bias+relu)
__device__ float   g_as1[NN * H1];
__device__ float   g_ad1[NN * H1];
__device__ __half2 g_h2h[(size_t)NN * C2 / 2];
__device__ float   g_as2[NN];
__device__ float   g_ad2[NN];
// CSR by dst
__device__ int g_deg[NN];
__device__ int g_cur[NN];
__device__ int g_row[NN + 1];
__device__ int g_srcs[ET];

__device__ __forceinline__ float lrelu(float v) {
    return v > 0.f ? v : NEG_SLOPE * v;
}

// online-softmax combine: (m,s) <- (m,s) ⊕ (om,os); NaN-safe for -inf pairs
__device__ __forceinline__ void osm_combine(float& m, float& s, float om, float os) {
    float nm = fmaxf(m, om);
    s = s * __expf(fmaxf(m - nm, -88.f)) + os * __expf(fmaxf(om - nm, -88.f));
    m = nm;
}

// ---------------- CSR build ----------------
__global__ void zero_counts_kernel() {
    int i = blockIdx.x * blockDim.x + threadIdx.x;
    if (i < NN) { g_deg[i] = 0; g_cur[i] = 0; }
}

__global__ void hist_kernel(const int* __restrict__ ei) {
    int e = blockIdx.x * blockDim.x + threadIdx.x;
    if (e >= ET) return;
    int d = (e < EE) ? ei[EE + e] : (e - EE);
    atomicAdd(&g_deg[d], 1);
}

// single-block exclusive scan of g_deg -> g_row  (1024 threads)
__global__ void scan_kernel() {
    __shared__ int warp_sums[32];
    const int CHUNK = (NN + 1023) / 1024;   // 49
    int t = threadIdx.x;
    int lane = t & 31, wid = t >> 5;
    int start = t * CHUNK;
    int local = 0;
    for (int i = 0; i < CHUNK; i++) {
        int idx = start + i;
        if (idx < NN) local += g_deg[idx];
    }
    int v = local;
    #pragma unroll
    for (int o = 1; o < 32; o <<= 1) {
        int n = __shfl_up_sync(0xFFFFFFFFu, v, o);
        if (lane >= o) v += n;
    }
    if (lane == 31) warp_sums[wid] = v;
    __syncthreads();
    if (wid == 0) {
        int w = warp_sums[lane];
        #pragma unroll
        for (int o = 1; o < 32; o <<= 1) {
            int n = __shfl_up_sync(0xFFFFFFFFu, w, o);
            if (lane >= o) w += n;
        }
        warp_sums[lane] = w;
    }
    __syncthreads();
    int excl = v - local + (wid > 0 ? warp_sums[wid - 1] : 0);
    int run = excl;
    for (int i = 0; i < CHUNK; i++) {
        int idx = start + i;
        if (idx < NN) {
            int dg = g_deg[idx];
            g_row[idx] = run;
            run += dg;
        }
    }
    if (t == 1023) g_row[NN] = run;   // == ET
}

__global__ void scatter_kernel(const int* __restrict__ ei) {
    int e = blockIdx.x * blockDim.x + threadIdx.x;
    if (e >= ET) return;
    int s, d;
    if (e < EE) { s = ei[e]; d = ei[EE + e]; } else { s = d = e - EE; }
    int pos = atomicAdd(&g_cur[d], 1);
    g_srcs[g_row[d] + pos] = s;
}

// ---------- SGEMM with fused fp16 store + attention-dot epilogue ----------
#define BM 128
#define BN 64
#define BK 16

__global__ __launch_bounds__(256, 2)
void sgemm_fused_kernel(const float* __restrict__ A,
                        const float* __restrict__ B,
                        __half2* __restrict__ Ch,
                        const float* __restrict__ att_s,
                        const float* __restrict__ att_d,
                        float* __restrict__ as_out,
                        float* __restrict__ ad_out,
                        int M, int N, int K, int Hs) {
    __shared__ float As[2][BK][BM];      // 16 KB
    __shared__ float Bs[2][BK][BN];      // 8 KB
    const int tid = threadIdx.x;
    const int tx = tid & 15;             // col group (4 cols)
    const int ty = tid >> 4;             // row group (8 rows)
    const int row0 = blockIdx.y * BM, col0 = blockIdx.x * BN;

    const int af0 = tid, af1 = tid + 256;
    const int ar0 = af0 >> 2, ac0 = (af0 & 3) * 4;
    const int ar1 = af1 >> 2, ac1 = (af1 & 3) * 4;
    const int br = tid >> 4, bc = (tid & 15) * 4;

    const int nk = K / BK;
    float4 pa0, pa1, pb;

    {
        int gr0 = row0 + ar0, gr1 = row0 + ar1;
        pa0 = (gr0 < M) ? *reinterpret_cast<const float4*>(A + (size_t)gr0 * K + ac0)
                        : make_float4(0.f, 0.f, 0.f, 0.f);
        pa1 = (gr1 < M) ? *reinterpret_cast<const float4*>(A + (size_t)gr1 * K + ac1)
                        : make_float4(0.f, 0.f, 0.f, 0.f);
        pb = *reinterpret_cast<const float4*>(B + (size_t)br * N + col0 + bc);
        As[0][ac0 + 0][ar0] = pa0.x; As[0][ac0 + 1][ar0] = pa0.y;
        As[0][ac0 + 2][ar0] = pa0.z; As[0][ac0 + 3][ar0] = pa0.w;
        As[0][ac1 + 0][ar1] = pa1.x; As[0][ac1 + 1][ar1] = pa1.y;
        As[0][ac1 + 2][ar1] = pa1.z; As[0][ac1 + 3][ar1] = pa1.w;
        *reinterpret_cast<float4*>(&Bs[0][br][bc]) = pb;
    }
    __syncthreads();

    float acc[8][4] = {};
    int buf = 0;
    for (int kt = 0; kt < nk; kt++) {
        if (kt + 1 < nk) {
            int k0 = (kt + 1) * BK;
            int gr0 = row0 + ar0, gr1 = row0 + ar1;
            pa0 = (gr0 < M) ? *reinterpret_cast<const float4*>(A + (size_t)gr0 * K + k0 + ac0)
                            : make_float4(0.f, 0.f, 0.f, 0.f);
            pa1 = (gr1 < M) ? *reinterpret_cast<const float4*>(A + (size_t)gr1 * K + k0 + ac1)
                            : make_float4(0.f, 0.f, 0.f, 0.f);
            pb = *reinterpret_cast<const float4*>(B + (size_t)(k0 + br) * N + col0 + bc);
        }
        #pragma unroll
        for (int k = 0; k < BK; k++) {
            float a[8], b[4];
            *reinterpret_cast<float4*>(a)     = *reinterpret_cast<const float4*>(&As[buf][k][ty * 8]);
            *reinterpret_cast<float4*>(a + 4) = *reinterpret_cast<const float4*>(&As[buf][k][ty * 8 + 4]);
            *reinterpret_cast<float4*>(b)     = *reinterpret_cast<const float4*>(&Bs[buf][k][tx * 4]);
            #pragma unroll
            for (int i = 0; i < 8; i++)
                #pragma unroll
                for (int j = 0; j < 4; j++)
                    acc[i][j] += a[i] * b[j];
        }
        if (kt + 1 < nk) {
            int nb = buf ^ 1;
            As[nb][ac0 + 0][ar0] = pa0.x; As[nb][ac0 + 1][ar0] = pa0.y;
            As[nb][ac0 + 2][ar0] = pa0.z; As[nb][ac0 + 3][ar0] = pa0.w;
            As[nb][ac1 + 0][ar1] = pa1.x; As[nb][ac1 + 1][ar1] = pa1.y;
            As[nb][ac1 + 2][ar1] = pa1.z; As[nb][ac1 + 3][ar1] = pa1.w;
            *reinterpret_cast<float4*>(&Bs[nb][br][bc]) = pb;
            __syncthreads();
            buf = nb;
        }
    }

    // fp16 store
    #pragma unroll
    for (int i = 0; i < 8; i++) {
        int gr = row0 + ty * 8 + i;
        if (gr < M) {
            __half2* dst = Ch + ((size_t)gr * N + col0 + tx * 4) / 2;
            dst[0] = __floats2half2_rn(acc[i][0], acc[i][1]);
            dst[1] = __floats2half2_rn(acc[i][2], acc[i][3]);
        }
    }

    // fused attention dots (one head per BN=64 column block)
    float sa4[4], da4[4];
    #pragma unroll
    for (int j = 0; j < 4; j++) {
        sa4[j] = att_s[col0 + tx * 4 + j];
        da4[j] = att_d[col0 + tx * 4 + j];
    }
    #pragma unroll
    for (int i = 0; i < 8; i++) {
        float ps = acc[i][0] * sa4[0] + acc[i][1] * sa4[1]
                 + acc[i][2] * sa4[2] + acc[i][3] * sa4[3];
        float pd = acc[i][0] * da4[0] + acc[i][1] * da4[1]
                 + acc[i][2] * da4[2] + acc[i][3] * da4[3];
        #pragma unroll
        for (int o = 1; o < 16; o <<= 1) {
            ps += __shfl_xor_sync(0xFFFFFFFFu, ps, o);
            pd += __shfl_xor_sync(0xFFFFFFFFu, pd, o);
        }
        int gr = row0 + ty * 8 + i;
        if (tx == 0 && gr < M) {
            as_out[gr * Hs + blockIdx.x] = ps;
            ad_out[gr * Hs + blockIdx.x] = pd;
        }
    }
}

// ---------------- fused layer1: 2 warps per node ----------------
// 64-thread group per dst node; each warp handles half the edges.
__global__ __launch_bounds__(256)
void gat1_fused_kernel(const float* __restrict__ b1) {
    __shared__ float sm_m[4][2][4];
    __shared__ float sm_s[4][2][4];
    __shared__ float sm_acc[4][256];

    int tid  = threadIdx.x;
    int grp  = tid >> 6;            // 0..3
    int sub  = (tid >> 5) & 1;      // warp within group
    int lane = tid & 31;
    int w = blockIdx.x * 4 + grp;
    bool active = (w < NN);

    int beg = 0, end = 0;
    float4 adv = make_float4(0.f, 0.f, 0.f, 0.f);
    if (active) {
        beg = g_row[w]; end = g_row[w + 1];
        adv = *reinterpret_cast<const float4*>(g_ad1 + w * H1);
    }

    // online softmax over this warp's edge subset (64-thread coverage)
    float4 mx = make_float4(-INFINITY, -INFINITY, -INFINITY, -INFINITY);
    float4 sm = make_float4(0.f, 0.f, 0.f, 0.f);
    for (int i = beg + sub * 32 + lane; i < end; i += 64) {
        int s = g_srcs[i];
        float4 a = *reinterpret_cast<const float4*>(g_as1 + s * H1);
        float vx = lrelu(a.x + adv.x), vy = lrelu(a.y + adv.y);
        float vz = lrelu(a.z + adv.z), vw = lrelu(a.w + adv.w);
        float nx = fmaxf(mx.x, vx), ny = fmaxf(mx.y, vy);
        float nz = fmaxf(mx.z, vz), nw = fmaxf(mx.w, vw);
        sm.x = sm.x * __expf(mx.x - nx) + __expf(vx - nx);
        sm.y = sm.y * __expf(mx.y - ny) + __expf(vy - ny);
        sm.z = sm.z * __expf(mx.z - nz) + __expf(vz - nz);
        sm.w = sm.w * __expf(mx.w - nw) + __expf(vw - nw);
        mx.x = nx; mx.y = ny; mx.z = nz; mx.w = nw;
    }
    #pragma unroll
    for (int o = 1; o < 32; o <<= 1) {
        float om, os;
        om = __shfl_xor_sync(0xFFFFFFFFu, mx.x, o);
        os = __shfl_xor_sync(0xFFFFFFFFu, sm.x, o);
        osm_combine(mx.x, sm.x, om, os);
        om = __shfl_xor_sync(0xFFFFFFFFu, mx.y, o);
        os = __shfl_xor_sync(0xFFFFFFFFu, sm.y, o);
        osm_combine(mx.y, sm.y, om, os);
        om = __shfl_xor_sync(0xFFFFFFFFu, mx.z, o);
        os = __shfl_xor_sync(0xFFFFFFFFu, sm.z, o);
        osm_combine(mx.z, sm.z, om, os);
        om = __shfl_xor_sync(0xFFFFFFFFu, mx.w, o);
        os = __shfl_xor_sync(0xFFFFFFFFu, sm.w, o);
        osm_combine(mx.w, sm.w, om, os);
    }
    if (lane == 0) {
        sm_m[grp][sub][0] = mx.x; sm_m[grp][sub][1] = mx.y;
        sm_m[grp][sub][2] = mx.z; sm_m[grp][sub][3] = mx.w;
        sm_s[grp][sub][0] = sm.x; sm_s[grp][sub][1] = sm.y;
        sm_s[grp][sub][2] = sm.z; sm_s[grp][sub][3] = sm.w;
    }
    __syncthreads();

    int head = lane >> 3;
    float mh  = sm_m[grp][0][head];
    float shv = sm_s[grp][0][head];
    osm_combine(mh, shv, sm_m[grp][1][head], sm_s[grp][1][head]);
    float adh = (head == 0) ? adv.x : (head == 1) ? adv.y
              : (head == 2) ? adv.z : adv.w;
    float inv = 1.f / (shv + 1e-16f);

    // pass C: each warp gathers its half of the edges (odd/even split)
    float acc[8] = {};
    #pragma unroll 2
    for (int i = beg + sub; i < end; i += 2) {
        int s = g_srcs[i];                               // broadcast load
        float ash = g_as1[s * H1 + head];
        float alpha = __expf(lrelu(ash + adh) - mh) * inv;
        const uint4* hp = reinterpret_cast<const uint4*>(g_h1h + (size_t)s * (D1 / 2));
        uint4 u = hp[lane];
        float2 f0 = __half22float2(*reinterpret_cast<__half2*>(&u.x));
        float2 f1 = __half22float2(*reinterpret_cast<__half2*>(&u.y));
        float2 f2 = __half22float2(*reinterpret_cast<__half2*>(&u.z));
        float2 f3 = __half22float2(*reinterpret_cast<__half2*>(&u.w));
        acc[0] += f0.x * alpha; acc[1] += f0.y * alpha;
        acc[2] += f1.x * alpha; acc[3] += f1.y * alpha;
        acc[4] += f2.x * alpha; acc[5] += f2.y * alpha;
        acc[6] += f3.x * alpha; acc[7] += f3.y * alpha;
    }

    int cb = lane * 8;
    if (sub == 0) {
        #pragma unroll
        for (int j = 0; j < 8; j++) sm_acc[grp][cb + j] = acc[j];
    }
    __syncthreads();
    if (sub == 1 && active) {
        float* op = g_acc1 + (size_t)w * D1 + cb;
        #pragma unroll
        for (int j = 0; j < 8; j++) {
            float v = acc[j] + sm_acc[grp][cb + j] + b1[cb + j];
            op[j] = v > 0.f ? v : 0.f;
        }
    }
}

// ---------------- fused layer2: 2 warps per node ----------------
__global__ __launch_bounds__(256)
void gat2_fused_kernel(const float* __restrict__ b2,
                       float* __restrict__ out) {
    __shared__ float sm_m[4][2];
    __shared__ float sm_s[4][2];
    __shared__ float sm_acc[4][64];

    int tid  = threadIdx.x;
    int grp  = tid >> 6;
    int sub  = (tid >> 5) & 1;
    int lane = tid & 31;
    int w = blockIdx.x * 4 + grp;
    bool active = (w < NN);

    int beg = 0, end = 0;
    float ad = 0.f;
    if (active) { beg = g_row[w]; end = g_row[w + 1]; ad = g_ad2[w]; }

    float mxv = -INFINITY, smv = 0.f;
    for (int i = beg + sub * 32 + lane; i < end; i += 64) {
        int s = g_srcs[i];
        float v = lrelu(g_as2[s] + ad);
        float nm = fmaxf(mxv, v);
        smv = smv * __expf(mxv - nm) + __expf(v - nm);
        mxv = nm;
    }
    #pragma unroll
    for (int o = 1; o < 32; o <<= 1) {
        float om = __shfl_xor_sync(0xFFFFFFFFu, mxv, o);
        float os = __shfl_xor_sync(0xFFFFFFFFu, smv, o);
        osm_combine(mxv, smv, om, os);
    }
    if (lane == 0) { sm_m[grp][sub] = mxv; sm_s[grp][sub] = smv; }
    __syncthreads();

    float mh = sm_m[grp][0], shv = sm_s[grp][0];
    osm_combine(mh, shv, sm_m[grp][1], sm_s[grp][1]);
    float inv = 1.f / (shv + 1e-16f);

    float a0 = 0.f, a1 = 0.f;
    #pragma unroll 2
    for (int i = beg + sub; i < end; i += 2) {
        int s = g_srcs[i];
        float alpha = __expf(lrelu(g_as2[s] + ad) - mh) * inv;
        __half2 hv = g_h2h[(size_t)s * (C2 / 2) + lane];
        float2 v = __half22float2(hv);
        a0 += v.x * alpha;
        a1 += v.y * alpha;
    }
    if (sub == 0) {
        sm_acc[grp][2 * lane]     = a0;
        sm_acc[grp][2 * lane + 1] = a1;
    }
    __syncthreads();
    if (sub == 1 && active) {
        float* op = out + (size_t)w * C2 + 2 * lane;
        op[0] = a0 + sm_acc[grp][2 * lane]     + b2[2 * lane];
        op[1] = a1 + sm_acc[grp][2 * lane + 1] + b2[2 * lane + 1];
    }
}

extern "C" void kernel_launch(void* const* d_in, const int* in_sizes, int n_in,
                              void* d_out, int out_size) {
    const float* x     = (const float*)d_in[0];
    const int*   ei    = (const int*)d_in[1];     // int32
    const float* W1    = (const float*)d_in[2];
    const float* at_s1 = (const float*)d_in[3];
    const float* at_d1 = (const float*)d_in[4];
    const float* b1    = (const float*)d_in[5];
    const float* W2    = (const float*)d_in[6];
    const float* at_s2 = (const float*)d_in[7];
    const float* at_d2 = (const float*)d_in[8];
    const float* b2    = (const float*)d_in[9];
    float* out = (float*)d_out;

    static float*   p_acc1 = nullptr;
    static __half2* p_h1h  = nullptr;
    static __half2* p_h2h  = nullptr;
    static float *p_as1, *p_ad1, *p_as2, *p_ad2;
    static cudaStream_t s_side = nullptr;
    static cudaEvent_t  ev_root = nullptr, ev_csr = nullptr;
    if (!p_acc1) {   // address lookup + stream/event creation (first call is
                     // the un-captured correctness run; no device mem alloc)
        cudaGetSymbolAddress((void**)&p_acc1, g_acc1);
        cudaGetSymbolAddress((void**)&p_h1h, g_h1h);
        cudaGetSymbolAddress((void**)&p_h2h, g_h2h);
        cudaGetSymbolAddress((void**)&p_as1, g_as1);
        cudaGetSymbolAddress((void**)&p_ad1, g_ad1);
        cudaGetSymbolAddress((void**)&p_as2, g_as2);
        cudaGetSymbolAddress((void**)&p_ad2, g_ad2);
        cudaStreamCreateWithFlags(&s_side, cudaStreamNonBlocking);
        cudaEventCreateWithFlags(&ev_root, cudaEventDisableTiming);
        cudaEventCreateWithFlags(&ev_csr, cudaEventDisableTiming);
    }

    // ---- fork: CSR build on side stream, overlapped with layer-1 GEMM ----
    cudaEventRecord(ev_root, (cudaStream_t)0);
    cudaStreamWaitEvent(s_side, ev_root, 0);
    zero_counts_kernel<<<(NN + 255) / 256, 256, 0, s_side>>>();
    hist_kernel<<<(ET + 255) / 256, 256, 0, s_side>>>(ei);
    scan_kernel<<<1, 1024, 0, s_side>>>();
    scatter_kernel<<<(ET + 255) / 256, 256, 0, s_side>>>(ei);
    cudaEventRecord(ev_csr, s_side);

    // ---- layer 1 (main stream) ----
    sgemm_fused_kernel<<<dim3(D1 / BN, (NN + BM - 1) / BM), 256>>>(
        x, W1, p_h1h, at_s1, at_d1, p_as1, p_ad1, NN, D1, IN1, H1);
    cudaStreamWaitEvent((cudaStream_t)0, ev_csr, 0);   // join CSR
    gat1_fused_kernel<<<(NN + 3) / 4, 256>>>(b1);

    // ---- layer 2 ----
    sgemm_fused_kernel<<<dim3(C2 / BN, (NN + BM - 1) / BM), 256>>>(
        p_acc1, W2, p_h2h, at_s2, at_d2, p_as2, p_ad2, NN, C2, D1, 1);
    gat2_fused_kernel<<<(NN + 3) / 4, 256>>>(b2, out);
}

// round 10
// speedup vs baseline: 1.7644x; 1.7644x over previous
#include <cuda_runtime.h>
#include <cuda_fp16.h>
#include <math.h>

// Problem constants (fixed for this dataset)
#define NN 50000
#define EE 800000
#define ET (EE + NN)      // 850000 edges incl. self loops
#define H1 4
#define C1 64
#define D1 256            // H1*C1
#define C2 64
#define IN1 128
#define NEG_SLOPE 0.2f

// ---------------- scratch (device globals, no runtime alloc) ----------------
__device__ __half2 g_h1h[(size_t)NN * D1 / 2];   // fp16 h1 (gather source)
__device__ float   g_acc1[(size_t)NN * D1];      // layer1 output (post bias+relu)
__device__ float   g_as1[NN * H1];
__device__ float   g_ad1[NN * H1];
__device__ __half2 g_h2h[(size_t)NN * C2 / 2];
__device__ float   g_as2[NN];
__device__ float   g_ad2[NN];
// CSR by dst
__device__ int g_deg[NN];
__device__ int g_cur[NN];
__device__ int g_row[NN + 1];
__device__ int g_srcs[ET];

__device__ __forceinline__ float lrelu(float v) {
    return v > 0.f ? v : NEG_SLOPE * v;
}

// online-softmax combine: (m,s) <- (m,s) ⊕ (om,os); NaN-safe for -inf pairs
__device__ __forceinline__ void osm_combine(float& m, float& s, float om, float os) {
    float nm = fmaxf(m, om);
    s = s * __expf(fmaxf(m - nm, -88.f)) + os * __expf(fmaxf(om - nm, -88.f));
    m = nm;
}

// ---------------- CSR build ----------------
__global__ void zero_counts_kernel() {
    int i = blockIdx.x * blockDim.x + threadIdx.x;
    if (i < NN) { g_deg[i] = 0; g_cur[i] = 0; }
}

__global__ void hist_kernel(const int* __restrict__ ei) {
    int e = blockIdx.x * blockDim.x + threadIdx.x;
    if (e >= ET) return;
    int d = (e < EE) ? ei[EE + e] : (e - EE);
    atomicAdd(&g_deg[d], 1);
}

// single-block exclusive scan of g_deg -> g_row  (1024 threads)
__global__ void scan_kernel() {
    __shared__ int warp_sums[32];
    const int CHUNK = (NN + 1023) / 1024;   // 49
    int t = threadIdx.x;
    int lane = t & 31, wid = t >> 5;
    int start = t * CHUNK;
    int local = 0;
    for (int i = 0; i < CHUNK; i++) {
        int idx = start + i;
        if (idx < NN) local += g_deg[idx];
    }
    int v = local;
    #pragma unroll
    for (int o = 1; o < 32; o <<= 1) {
        int n = __shfl_up_sync(0xFFFFFFFFu, v, o);
        if (lane >= o) v += n;
    }
    if (lane == 31) warp_sums[wid] = v;
    __syncthreads();
    if (wid == 0) {
        int w = warp_sums[lane];
        #pragma unroll
        for (int o = 1; o < 32; o <<= 1) {
            int n = __shfl_up_sync(0xFFFFFFFFu, w, o);
            if (lane >= o) w += n;
        }
        warp_sums[lane] = w;
    }
    __syncthreads();
    int excl = v - local + (wid > 0 ? warp_sums[wid - 1] : 0);
    int run = excl;
    for (int i = 0; i < CHUNK; i++) {
        int idx = start + i;
        if (idx < NN) {
            int dg = g_deg[idx];
            g_row[idx] = run;
            run += dg;
        }
    }
    if (t == 1023) g_row[NN] = run;   // == ET
}

__global__ void scatter_kernel(const int* __restrict__ ei) {
    int e = blockIdx.x * blockDim.x + threadIdx.x;
    if (e >= ET) return;
    int s, d;
    if (e < EE) { s = ei[e]; d = ei[EE + e]; } else { s = d = e - EE; }
    int pos = atomicAdd(&g_cur[d], 1);
    g_srcs[g_row[d] + pos] = s;
}

// ---------- SGEMM with fused fp16 store + attention-dot epilogue ----------
#define BM 128
#define BN 64
#define BK 16

__global__ __launch_bounds__(256, 2)
void sgemm_fused_kernel(const float* __restrict__ A,
                        const float* __restrict__ B,
                        __half2* __restrict__ Ch,
                        const float* __restrict__ att_s,
                        const float* __restrict__ att_d,
                        float* __restrict__ as_out,
                        float* __restrict__ ad_out,
                        int M, int N, int K, int Hs) {
    __shared__ float As[2][BK][BM];      // 16 KB
    __shared__ float Bs[2][BK][BN];      // 8 KB
    const int tid = threadIdx.x;
    const int tx = tid & 15;             // col group (4 cols)
    const int ty = tid >> 4;             // row group (8 rows)
    const int row0 = blockIdx.y * BM, col0 = blockIdx.x * BN;

    const int af0 = tid, af1 = tid + 256;
    const int ar0 = af0 >> 2, ac0 = (af0 & 3) * 4;
    const int ar1 = af1 >> 2, ac1 = (af1 & 3) * 4;
    const int br = tid >> 4, bc = (tid & 15) * 4;

    const int nk = K / BK;
    float4 pa0, pa1, pb;

    {
        int gr0 = row0 + ar0, gr1 = row0 + ar1;
        pa0 = (gr0 < M) ? *reinterpret_cast<const float4*>(A + (size_t)gr0 * K + ac0)
                        : make_float4(0.f, 0.f, 0.f, 0.f);
        pa1 = (gr1 < M) ? *reinterpret_cast<const float4*>(A + (size_t)gr1 * K + ac1)
                        : make_float4(0.f, 0.f, 0.f, 0.f);
        pb = *reinterpret_cast<const float4*>(B + (size_t)br * N + col0 + bc);
        As[0][ac0 + 0][ar0] = pa0.x; As[0][ac0 + 1][ar0] = pa0.y;
        As[0][ac0 + 2][ar0] = pa0.z; As[0][ac0 + 3][ar0] = pa0.w;
        As[0][ac1 + 0][ar1] = pa1.x; As[0][ac1 + 1][ar1] = pa1.y;
        As[0][ac1 + 2][ar1] = pa1.z; As[0][ac1 + 3][ar1] = pa1.w;
        *reinterpret_cast<float4*>(&Bs[0][br][bc]) = pb;
    }
    __syncthreads();

    float acc[8][4] = {};
    int buf = 0;
    for (int kt = 0; kt < nk; kt++) {
        if (kt + 1 < nk) {
            int k0 = (kt + 1) * BK;
            int gr0 = row0 + ar0, gr1 = row0 + ar1;
            pa0 = (gr0 < M) ? *reinterpret_cast<const float4*>(A + (size_t)gr0 * K + k0 + ac0)
                            : make_float4(0.f, 0.f, 0.f, 0.f);
            pa1 = (gr1 < M) ? *reinterpret_cast<const float4*>(A + (size_t)gr1 * K + k0 + ac1)
                            : make_float4(0.f, 0.f, 0.f, 0.f);
            pb = *reinterpret_cast<const float4*>(B + (size_t)(k0 + br) * N + col0 + bc);
        }
        #pragma unroll
        for (int k = 0; k < BK; k++) {
            float a[8], b[4];
            *reinterpret_cast<float4*>(a)     = *reinterpret_cast<const float4*>(&As[buf][k][ty * 8]);
            *reinterpret_cast<float4*>(a + 4) = *reinterpret_cast<const float4*>(&As[buf][k][ty * 8 + 4]);
            *reinterpret_cast<float4*>(b)     = *reinterpret_cast<const float4*>(&Bs[buf][k][tx * 4]);
            #pragma unroll
            for (int i = 0; i < 8; i++)
                #pragma unroll
                for (int j = 0; j < 4; j++)
                    acc[i][j] += a[i] * b[j];
        }
        if (kt + 1 < nk) {
            int nb = buf ^ 1;
            As[nb][ac0 + 0][ar0] = pa0.x; As[nb][ac0 + 1][ar0] = pa0.y;
            As[nb][ac0 + 2][ar0] = pa0.z; As[nb][ac0 + 3][ar0] = pa0.w;
            As[nb][ac1 + 0][ar1] = pa1.x; As[nb][ac1 + 1][ar1] = pa1.y;
            As[nb][ac1 + 2][ar1] = pa1.z; As[nb][ac1 + 3][ar1] = pa1.w;
            *reinterpret_cast<float4*>(&Bs[nb][br][bc]) = pb;
            __syncthreads();
            buf = nb;
        }
    }

    // fp16 store
    #pragma unroll
    for (int i = 0; i < 8; i++) {
        int gr = row0 + ty * 8 + i;
        if (gr < M) {
            __half2* dst = Ch + ((size_t)gr * N + col0 + tx * 4) / 2;
            dst[0] = __floats2half2_rn(acc[i][0], acc[i][1]);
            dst[1] = __floats2half2_rn(acc[i][2], acc[i][3]);
        }
    }

    // fused attention dots (one head per BN=64 column block)
    float sa4[4], da4[4];
    #pragma unroll
    for (int j = 0; j < 4; j++) {
        sa4[j] = att_s[col0 + tx * 4 + j];
        da4[j] = att_d[col0 + tx * 4 + j];
    }
    #pragma unroll
    for (int i = 0; i < 8; i++) {
        float ps = acc[i][0] * sa4[0] + acc[i][1] * sa4[1]
                 + acc[i][2] * sa4[2] + acc[i][3] * sa4[3];
        float pd = acc[i][0] * da4[0] + acc[i][1] * da4[1]
                 + acc[i][2] * da4[2] + acc[i][3] * da4[3];
        #pragma unroll
        for (int o = 1; o < 16; o <<= 1) {
            ps += __shfl_xor_sync(0xFFFFFFFFu, ps, o);
            pd += __shfl_xor_sync(0xFFFFFFFFu, pd, o);
        }
        int gr = row0 + ty * 8 + i;
        if (tx == 0 && gr < M) {
            as_out[gr * Hs + blockIdx.x] = ps;
            ad_out[gr * Hs + blockIdx.x] = pd;
        }
    }
}

// ---------------- fused layer1: online softmax + fp16 gather + bias + relu
// one warp per dst node; lane covers 8 cols (head = lane>>3)
__global__ void gat1_fused_kernel(const float* __restrict__ b1) {
    int w = (blockIdx.x * blockDim.x + threadIdx.x) >> 5;
    int lane = threadIdx.x & 31;
    if (w >= NN) return;
    int beg = g_row[w], end = g_row[w + 1];

    float4 adv = *reinterpret_cast<const float4*>(g_ad1 + w * H1);

    // single pass: online softmax (per-lane running max + rescaled sum)
    float4 mx = make_float4(-INFINITY, -INFINITY, -INFINITY, -INFINITY);
    float4 sm = make_float4(0.f, 0.f, 0.f, 0.f);
    for (int i = beg + lane; i < end; i += 32) {
        int s = g_srcs[i];
        float4 a = *reinterpret_cast<const float4*>(g_as1 + s * H1);
        float vx = lrelu(a.x + adv.x), vy = lrelu(a.y + adv.y);
        float vz = lrelu(a.z + adv.z), vw = lrelu(a.w + adv.w);
        float nx = fmaxf(mx.x, vx), ny = fmaxf(mx.y, vy);
        float nz = fmaxf(mx.z, vz), nw = fmaxf(mx.w, vw);
        sm.x = sm.x * __expf(mx.x - nx) + __expf(vx - nx);
        sm.y = sm.y * __expf(mx.y - ny) + __expf(vy - ny);
        sm.z = sm.z * __expf(mx.z - nz) + __expf(vz - nz);
        sm.w = sm.w * __expf(mx.w - nw) + __expf(vw - nw);
        mx.x = nx; mx.y = ny; mx.z = nz; mx.w = nw;
    }
    // lane combine
    #pragma unroll
    for (int o = 1; o < 32; o <<= 1) {
        float omx, osx;
        omx = __shfl_xor_sync(0xFFFFFFFFu, mx.x, o);
        osx = __shfl_xor_sync(0xFFFFFFFFu, sm.x, o);
        osm_combine(mx.x, sm.x, omx, osx);
        omx = __shfl_xor_sync(0xFFFFFFFFu, mx.y, o);
        osx = __shfl_xor_sync(0xFFFFFFFFu, sm.y, o);
        osm_combine(mx.y, sm.y, omx, osx);
        omx = __shfl_xor_sync(0xFFFFFFFFu, mx.z, o);
        osx = __shfl_xor_sync(0xFFFFFFFFu, sm.z, o);
        osm_combine(mx.z, sm.z, omx, osx);
        omx = __shfl_xor_sync(0xFFFFFFFFu, mx.w, o);
        osx = __shfl_xor_sync(0xFFFFFFFFu, sm.w, o);
        osm_combine(mx.w, sm.w, omx, osx);
    }

    int head = lane >> 3;
    float mh  = (head == 0) ? mx.x : (head == 1) ? mx.y : (head == 2) ? mx.z : mx.w;
    float shv = (head == 0) ? sm.x : (head == 1) ? sm.y : (head == 2) ? sm.z : sm.w;
    float adh = (head == 0) ? adv.x : (head == 1) ? adv.y : (head == 2) ? adv.z : adv.w;
    float inv = 1.f / (shv + 1e-16f);

    // pass C: direct per-edge gather + fp32 accumulate (warp-uniform broadcast)
    float acc[8] = {};
    #pragma unroll 4
    for (int i = beg; i < end; i++) {
        int s = g_srcs[i];                               // broadcast load
        float ash = g_as1[s * H1 + head];
        float alpha = __expf(lrelu(ash + adh) - mh) * inv;
        const uint4* hp = reinterpret_cast<const uint4*>(g_h1h + (size_t)s * (D1 / 2));
        uint4 u = hp[lane];
        float2 f0 = __half22float2(*reinterpret_cast<__half2*>(&u.x));
        float2 f1 = __half22float2(*reinterpret_cast<__half2*>(&u.y));
        float2 f2 = __half22float2(*reinterpret_cast<__half2*>(&u.z));
        float2 f3 = __half22float2(*reinterpret_cast<__half2*>(&u.w));
        acc[0] += f0.x * alpha; acc[1] += f0.y * alpha;
        acc[2] += f1.x * alpha; acc[3] += f1.y * alpha;
        acc[4] += f2.x * alpha; acc[5] += f2.y * alpha;
        acc[6] += f3.x * alpha; acc[7] += f3.y * alpha;
    }

    int cb = lane * 8;
    float* op = g_acc1 + (size_t)w * D1 + cb;
    #pragma unroll
    for (int j = 0; j < 8; j++) {
        float v = acc[j] + b1[cb + j];
        op[j] = v > 0.f ? v : 0.f;
    }
}

// ---------------- fused layer2: online softmax + fp16 gather + bias -------
__global__ void gat2_fused_kernel(const float* __restrict__ b2,
                                  float* __restrict__ out) {
    int w = (blockIdx.x * blockDim.x + threadIdx.x) >> 5;
    int lane = threadIdx.x & 31;
    if (w >= NN) return;
    int beg = g_row[w], end = g_row[w + 1];

    float ad = g_ad2[w];

    float mxv = -INFINITY, smv = 0.f;
    for (int i = beg + lane; i < end; i += 32) {
        int s = g_srcs[i];
        float v = lrelu(g_as2[s] + ad);
        float nm = fmaxf(mxv, v);
        smv = smv * __expf(mxv - nm) + __expf(v - nm);
        mxv = nm;
    }
    #pragma unroll
    for (int o = 1; o < 32; o <<= 1) {
        float om = __shfl_xor_sync(0xFFFFFFFFu, mxv, o);
        float os = __shfl_xor_sync(0xFFFFFFFFu, smv, o);
        osm_combine(mxv, smv, om, os);
    }
    float inv = 1.f / (smv + 1e-16f);

    float a0 = 0.f, a1 = 0.f;
    #pragma unroll 4
    for (int i = beg; i < end; i++) {
        int s = g_srcs[i];
        float alpha = __expf(lrelu(g_as2[s] + ad) - mxv) * inv;
        __half2 hv = g_h2h[(size_t)s * (C2 / 2) + lane];
        float2 v = __half22float2(hv);
        a0 += v.x * alpha;
        a1 += v.y * alpha;
    }
    float* op = out + (size_t)w * C2 + 2 * lane;
    op[0] = a0 + b2[2 * lane];
    op[1] = a1 + b2[2 * lane + 1];
}

extern "C" void kernel_launch(void* const* d_in, const int* in_sizes, int n_in,
                              void* d_out, int out_size) {
    const float* x     = (const float*)d_in[0];
    const int*   ei    = (const int*)d_in[1];     // int32
    const float* W1    = (const float*)d_in[2];
    const float* at_s1 = (const float*)d_in[3];
    const float* at_d1 = (const float*)d_in[4];
    const float* b1    = (const float*)d_in[5];
    const float* W2    = (const float*)d_in[6];
    const float* at_s2 = (const float*)d_in[7];
    const float* at_d2 = (const float*)d_in[8];
    const float* b2    = (const float*)d_in[9];
    float* out = (float*)d_out;

    static float*   p_acc1 = nullptr;
    static __half2* p_h1h  = nullptr;
    static __half2* p_h2h  = nullptr;
    static float *p_as1, *p_ad1, *p_as2, *p_ad2;
    static cudaStream_t s_side = nullptr;
    static cudaEvent_t  ev_root = nullptr, ev_csr = nullptr;
    if (!p_acc1) {   // address lookup + stream/event creation (first call is
                     // the un-captured correctness run; no device mem alloc)
        cudaGetSymbolAddress((void**)&p_acc1, g_acc1);
        cudaGetSymbolAddress((void**)&p_h1h, g_h1h);
        cudaGetSymbolAddress((void**)&p_h2h, g_h2h);
        cudaGetSymbolAddress((void**)&p_as1, g_as1);
        cudaGetSymbolAddress((void**)&p_ad1, g_ad1);
        cudaGetSymbolAddress((void**)&p_as2, g_as2);
        cudaGetSymbolAddress((void**)&p_ad2, g_ad2);
        cudaStreamCreateWithFlags(&s_side, cudaStreamNonBlocking);
        cudaEventCreateWithFlags(&ev_root, cudaEventDisableTiming);
        cudaEventCreateWithFlags(&ev_csr, cudaEventDisableTiming);
    }

    // ---- fork: CSR build on side stream, overlapped with layer-1 GEMM ----
    // Host launch order puts sgemm1 4th so the fixed ncu window (-s 5 -c 1,
    // which lands on our 4th launch) profiles it instead of scatter.
    cudaEventRecord(ev_root, (cudaStream_t)0);
    cudaStreamWaitEvent(s_side, ev_root, 0);
    zero_counts_kernel<<<(NN + 255) / 256, 256, 0, s_side>>>();   // #1
    hist_kernel<<<(ET + 255) / 256, 256, 0, s_side>>>(ei);        // #2
    scan_kernel<<<1, 1024, 0, s_side>>>();                        // #3

    // ---- layer 1 GEMM (main stream) ----                       // #4
    sgemm_fused_kernel<<<dim3(D1 / BN, (NN + BM - 1) / BM), 256>>>(
        x, W1, p_h1h, at_s1, at_d1, p_as1, p_ad1, NN, D1, IN1, H1);

    scatter_kernel<<<(ET + 255) / 256, 256, 0, s_side>>>(ei);     // #5
    cudaEventRecord(ev_csr, s_side);

    cudaStreamWaitEvent((cudaStream_t)0, ev_csr, 0);   // join CSR
    gat1_fused_kernel<<<(NN + 7) / 8, 256>>>(b1);                 // #6

    // ---- layer 2 ----
    sgemm_fused_kernel<<<dim3(C2 / BN, (NN + BM - 1) / BM), 256>>>(
        p_acc1, W2, p_h2h, at_s2, at_d2, p_as2, p_ad2, NN, C2, D1, 1);
    gat2_fused_kernel<<<(NN + 7) / 8, 256>>>(b2, out);
}

// round 12
// speedup vs baseline: 1.8072x; 1.0243x over previous
#include <cuda_runtime.h>
#include <cuda_fp16.h>
#include <math.h>

// Problem constants (fixed for this dataset)
#define NN 50000
#define EE 800000
#define ET (EE + NN)      // 850000 edges incl. self loops
#define H1 4
#define C1 64
#define D1 256            // H1*C1
#define C2 64
#define IN1 128
#define NEG_SLOPE 0.2f

// ---------------- scratch (device globals, no runtime alloc) ----------------
__device__ __half2 g_h1h[(size_t)NN * D1 / 2];   // fp16 h1 (gather source)
__device__ float   g_acc1[(size_t)NN * D1];      // layer1 output (post bias+relu)
__device__ float   g_as1[NN * H1];
__device__ float   g_ad1[NN * H1];
__device__ __half2 g_h2h[(size_t)NN * C2 / 2];
__device__ float   g_as2[NN];
__device__ float   g_ad2[NN];
// CSR by dst
__device__ int g_deg[NN];
__device__ int g_cur[NN];
__device__ int g_row[NN + 1];
__device__ int g_srcs[ET];

__device__ __forceinline__ float lrelu(float v) {
    return v > 0.f ? v : NEG_SLOPE * v;
}

// online-softmax combine: (m,s) <- (m,s) ⊕ (om,os); NaN-safe for -inf pairs
__device__ __forceinline__ void osm_combine(float& m, float& s, float om, float os) {
    float nm = fmaxf(m, om);
    s = s * __expf(fmaxf(m - nm, -88.f)) + os * __expf(fmaxf(om - nm, -88.f));
    m = nm;
}

__device__ __forceinline__ unsigned f2tf32(float f) {
    unsigned r;
    asm("cvt.rna.tf32.f32 %0, %1;" : "=r"(r) : "f"(f));
    return r;
}

// ---------------- CSR build ----------------
__global__ void zero_counts_kernel() {
    int i = blockIdx.x * blockDim.x + threadIdx.x;
    if (i < NN) { g_deg[i] = 0; g_cur[i] = 0; }
}

__global__ void hist_kernel(const int* __restrict__ ei) {
    int e = blockIdx.x * blockDim.x + threadIdx.x;
    if (e >= ET) return;
    int d = (e < EE) ? ei[EE + e] : (e - EE);
    atomicAdd(&g_deg[d], 1);
}

// single-block exclusive scan of g_deg -> g_row  (1024 threads)
__global__ void scan_kernel() {
    __shared__ int warp_sums[32];
    const int CHUNK = (NN + 1023) / 1024;   // 49
    int t = threadIdx.x;
    int lane = t & 31, wid = t >> 5;
    int start = t * CHUNK;
    int local = 0;
    for (int i = 0; i < CHUNK; i++) {
        int idx = start + i;
        if (idx < NN) local += g_deg[idx];
    }
    int v = local;
    #pragma unroll
    for (int o = 1; o < 32; o <<= 1) {
        int n = __shfl_up_sync(0xFFFFFFFFu, v, o);
        if (lane >= o) v += n;
    }
    if (lane == 31) warp_sums[wid] = v;
    __syncthreads();
    if (wid == 0) {
        int w = warp_sums[lane];
        #pragma unroll
        for (int o = 1; o < 32; o <<= 1) {
            int n = __shfl_up_sync(0xFFFFFFFFu, w, o);
            if (lane >= o) w += n;
        }
        warp_sums[lane] = w;
    }
    __syncthreads();
    int excl = v - local + (wid > 0 ? warp_sums[wid - 1] : 0);
    int run = excl;
    for (int i = 0; i < CHUNK; i++) {
        int idx = start + i;
        if (idx < NN) {
            int dg = g_deg[idx];
            g_row[idx] = run;
            run += dg;
        }
    }
    if (t == 1023) g_row[NN] = run;   // == ET
}

__global__ void scatter_kernel(const int* __restrict__ ei) {
    int e = blockIdx.x * blockDim.x + threadIdx.x;
    if (e >= ET) return;
    int s, d;
    if (e < EE) { s = ei[e]; d = ei[EE + e]; } else { s = d = e - EE; }
    int pos = atomicAdd(&g_cur[d], 1);
    g_srcs[g_row[d] + pos] = s;
}

// ---------- tf32 tensor-core GEMM + fp16 store + attention-dot epilogue ----
// C fp16 = A[M,K] @ B[K,N]; one head per BN=64 col block.
// 8 warps: warp_m = wid&3 (4), warp_n = wid>>2 (2); warp tile 32x32.
// mma.sync.aligned.m16n8k8 tf32. Smem tiles stored in fragment order.
#define BM 128
#define BN 64
#define BK 16

__global__ __launch_bounds__(256, 2)
void sgemm_fused_kernel(const float* __restrict__ A,
                        const float* __restrict__ B,
                        __half2* __restrict__ Ch,
                        const float* __restrict__ att_s,
                        const float* __restrict__ att_d,
                        float* __restrict__ as_out,
                        float* __restrict__ ad_out,
                        int M, int N, int K, int Hs) {
    // A_sm[buf][kc][mt][lane*4+slot] : 16 KB ; B_sm[buf][kc][nt][lane*2+slot] : 8 KB
    __shared__ unsigned A_sm[2][2][8][128];
    __shared__ unsigned B_sm[2][2][8][64];
    __shared__ float red_s[2][BM];
    __shared__ float red_d[2][BM];

    const int tid  = threadIdx.x;
    const int lane = tid & 31;
    const int wid  = tid >> 5;
    const int wm   = wid & 3;          // warp m index (0..3)
    const int wn   = wid >> 2;         // warp n index (0..1)
    const int g    = lane >> 2;        // groupID
    const int t4   = lane & 3;         // threadID in group
    const int row0 = blockIdx.y * BM, col0 = blockIdx.x * BN;

    // global A load mapping: 2 float4/thread
    const int ar0 = tid >> 2,          ac0 = (tid & 3) * 4;
    const int ar1 = (tid + 256) >> 2;  // same ac
    // global B load mapping: 1 float4/thread
    const int bk  = tid >> 4,          bn4 = (tid & 15) * 4;

    const int nk = K / BK;
    float4 pa0, pa1, pb;

    // ---- load helpers (macros keep regs local) ----
    #define LOAD_REGS(k0)                                                        \
        do {                                                                     \
            int gr0 = row0 + ar0, gr1 = row0 + ar1;                              \
            pa0 = (gr0 < M) ? *reinterpret_cast<const float4*>(A + (size_t)gr0 * K + (k0) + ac0) \
                            : make_float4(0.f, 0.f, 0.f, 0.f);                   \
            pa1 = (gr1 < M) ? *reinterpret_cast<const float4*>(A + (size_t)gr1 * K + (k0) + ac0) \
                            : make_float4(0.f, 0.f, 0.f, 0.f);                   \
            pb = *reinterpret_cast<const float4*>(B + (size_t)((k0) + bk) * N + col0 + bn4); \
        } while (0)

    #define STORE_A1(bufi, r, v, j)                                              \
        do {                                                                     \
            int k = ac0 + (j);                                                   \
            int kc = k >> 3, c = k & 7;                                          \
            int mt = (r) >> 4, rr = (r) & 15;                                    \
            int ln = ((rr & 7) << 2) | (c & 3);                                  \
            int sl = ((rr >> 3) & 1) | (((c >> 2) & 1) << 1);                    \
            A_sm[bufi][kc][mt][ln * 4 + sl] = f2tf32(v);                         \
        } while (0)

    #define STORE_SMEM(bufi)                                                     \
        do {                                                                     \
            STORE_A1(bufi, ar0, pa0.x, 0); STORE_A1(bufi, ar0, pa0.y, 1);        \
            STORE_A1(bufi, ar0, pa0.z, 2); STORE_A1(bufi, ar0, pa0.w, 3);        \
            STORE_A1(bufi, ar1, pa1.x, 0); STORE_A1(bufi, ar1, pa1.y, 1);        \
            STORE_A1(bufi, ar1, pa1.z, 2); STORE_A1(bufi, ar1, pa1.w, 3);        \
            int kcb = bk >> 3, kk = bk & 7, slB = kk >> 2;                       \
            int ntb = bn4 >> 3, nnb = bn4 & 7;                                   \
            B_sm[bufi][kcb][ntb][((nnb + 0) * 4 + (kk & 3)) * 2 + slB] = f2tf32(pb.x); \
            B_sm[bufi][kcb][ntb][((nnb + 1) * 4 + (kk & 3)) * 2 + slB] = f2tf32(pb.y); \
            B_sm[bufi][kcb][ntb][((nnb + 2) * 4 + (kk & 3)) * 2 + slB] = f2tf32(pb.z); \
            B_sm[bufi][kcb][ntb][((nnb + 3) * 4 + (kk & 3)) * 2 + slB] = f2tf32(pb.w); \
        } while (0)

    LOAD_REGS(0);
    STORE_SMEM(0);
    __syncthreads();

    float acc[2][4][4] = {};
    int buf = 0;
    for (int kt = 0; kt < nk; kt++) {
        if (kt + 1 < nk) LOAD_REGS((kt + 1) * BK);
        #pragma unroll
        for (int kc = 0; kc < 2; kc++) {
            uint4 af[2];
            #pragma unroll
            for (int mtl = 0; mtl < 2; mtl++)
                af[mtl] = *reinterpret_cast<const uint4*>(&A_sm[buf][kc][wm * 2 + mtl][lane * 4]);
            uint2 bf[4];
            #pragma unroll
            for (int ntl = 0; ntl < 4; ntl++)
                bf[ntl] = *reinterpret_cast<const uint2*>(&B_sm[buf][kc][wn * 4 + ntl][lane * 2]);
            #pragma unroll
            for (int mtl = 0; mtl < 2; mtl++)
                #pragma unroll
                for (int ntl = 0; ntl < 4; ntl++)
                    asm volatile(
                        "mma.sync.aligned.m16n8k8.row.col.f32.tf32.tf32.f32 "
                        "{%0,%1,%2,%3}, {%4,%5,%6,%7}, {%8,%9}, {%0,%1,%2,%3};"
                        : "+f"(acc[mtl][ntl][0]), "+f"(acc[mtl][ntl][1]),
                          "+f"(acc[mtl][ntl][2]), "+f"(acc[mtl][ntl][3])
                        : "r"(af[mtl].x), "r"(af[mtl].y), "r"(af[mtl].z), "r"(af[mtl].w),
                          "r"(bf[ntl].x), "r"(bf[ntl].y));
        }
        if (kt + 1 < nk) {
            STORE_SMEM(buf ^ 1);
            __syncthreads();
            buf ^= 1;
        }
    }

    // ---- epilogue: fp16 store + per-warp attention partial dots ----
    float ps[2][2] = {}, pd[2][2] = {};
    #pragma unroll
    for (int mtl = 0; mtl < 2; mtl++) {
        int rlo = row0 + wm * 32 + mtl * 16 + g;
        int rhi = rlo + 8;
        #pragma unroll
        for (int ntl = 0; ntl < 4; ntl++) {
            int cn = wn * 32 + ntl * 8 + 2 * t4;     // col within this N block
            float a0 = acc[mtl][ntl][0], a1 = acc[mtl][ntl][1];
            float a2 = acc[mtl][ntl][2], a3 = acc[mtl][ntl][3];
            if (rlo < M)
                Ch[((size_t)rlo * N + col0 + cn) / 2] = __floats2half2_rn(a0, a1);
            if (rhi < M)
                Ch[((size_t)rhi * N + col0 + cn) / 2] = __floats2half2_rn(a2, a3);
            float s0 = att_s[col0 + cn], s1 = att_s[col0 + cn + 1];
            float d0 = att_d[col0 + cn], d1 = att_d[col0 + cn + 1];
            ps[mtl][0] += a0 * s0 + a1 * s1;  pd[mtl][0] += a0 * d0 + a1 * d1;
            ps[mtl][1] += a2 * s0 + a3 * s1;  pd[mtl][1] += a2 * d0 + a3 * d1;
        }
        // reduce across the 4 lanes sharing each row (t4 group)
        #pragma unroll
        for (int o = 1; o < 4; o <<= 1) {
            ps[mtl][0] += __shfl_xor_sync(0xFFFFFFFFu, ps[mtl][0], o);
            ps[mtl][1] += __shfl_xor_sync(0xFFFFFFFFu, ps[mtl][1], o);
            pd[mtl][0] += __shfl_xor_sync(0xFFFFFFFFu, pd[mtl][0], o);
            pd[mtl][1] += __shfl_xor_sync(0xFFFFFFFFu, pd[mtl][1], o);
        }
        if (t4 == 0) {
            int rloc = wm * 32 + mtl * 16 + g;
            red_s[wn][rloc]     = ps[mtl][0];
            red_s[wn][rloc + 8] = ps[mtl][1];
            red_d[wn][rloc]     = pd[mtl][0];
            red_d[wn][rloc + 8] = pd[mtl][1];
        }
    }
    __syncthreads();
    if (tid < BM) {
        int r = row0 + tid;
        if (r < M) {
            as_out[r * Hs + blockIdx.x] = red_s[0][tid] + red_s[1][tid];
            ad_out[r * Hs + blockIdx.x] = red_d[0][tid] + red_d[1][tid];
        }
    }
    #undef LOAD_REGS
    #undef STORE_A1
    #undef STORE_SMEM
}

// ---------------- fused layer1: online softmax + fp16 gather + bias + relu
// one warp per dst node; lane covers 8 cols (head = lane>>3)
__global__ void gat1_fused_kernel(const float* __restrict__ b1) {
    int w = (blockIdx.x * blockDim.x + threadIdx.x) >> 5;
    int lane = threadIdx.x & 31;
    if (w >= NN) return;
    int beg = g_row[w], end = g_row[w + 1];

    float4 adv = *reinterpret_cast<const float4*>(g_ad1 + w * H1);

    // single pass: online softmax (per-lane running max + rescaled sum)
    float4 mx = make_float4(-INFINITY, -INFINITY, -INFINITY, -INFINITY);
    float4 sm = make_float4(0.f, 0.f, 0.f, 0.f);
    for (int i = beg + lane; i < end; i += 32) {
        int s = g_srcs[i];
        float4 a = *reinterpret_cast<const float4*>(g_as1 + s * H1);
        float vx = lrelu(a.x + adv.x), vy = lrelu(a.y + adv.y);
        float vz = lrelu(a.z + adv.z), vw = lrelu(a.w + adv.w);
        float nx = fmaxf(mx.x, vx), ny = fmaxf(mx.y, vy);
        float nz = fmaxf(mx.z, vz), nw = fmaxf(mx.w, vw);
        sm.x = sm.x * __expf(mx.x - nx) + __expf(vx - nx);
        sm.y = sm.y * __expf(mx.y - ny) + __expf(vy - ny);
        sm.z = sm.z * __expf(mx.z - nz) + __expf(vz - nz);
        sm.w = sm.w * __expf(mx.w - nw) + __expf(vw - nw);
        mx.x = nx; mx.y = ny; mx.z = nz; mx.w = nw;
    }
    // lane combine
    #pragma unroll
    for (int o = 1; o < 32; o <<= 1) {
        float omx, osx;
        omx = __shfl_xor_sync(0xFFFFFFFFu, mx.x, o);
        osx = __shfl_xor_sync(0xFFFFFFFFu, sm.x, o);
        osm_combine(mx.x, sm.x, omx, osx);
        omx = __shfl_xor_sync(0xFFFFFFFFu, mx.y, o);
        osx = __shfl_xor_sync(0xFFFFFFFFu, sm.y, o);
        osm_combine(mx.y, sm.y, omx, osx);
        omx = __shfl_xor_sync(0xFFFFFFFFu, mx.z, o);
        osx = __shfl_xor_sync(0xFFFFFFFFu, sm.z, o);
        osm_combine(mx.z, sm.z, omx, osx);
        omx = __shfl_xor_sync(0xFFFFFFFFu, mx.w, o);
        osx = __shfl_xor_sync(0xFFFFFFFFu, sm.w, o);
        osm_combine(mx.w, sm.w, omx, osx);
    }

    int head = lane >> 3;
    float mh  = (head == 0) ? mx.x : (head == 1) ? mx.y : (head == 2) ? mx.z : mx.w;
    float shv = (head == 0) ? sm.x : (head == 1) ? sm.y : (head == 2) ? sm.z : sm.w;
    float adh = (head == 0) ? adv.x : (head == 1) ? adv.y : (head == 2) ? adv.z : adv.w;
    float inv = 1.f / (shv + 1e-16f);

    // pass C: direct per-edge gather + fp32 accumulate (warp-uniform broadcast)
    float acc[8] = {};
    #pragma unroll 4
    for (int i = beg; i < end; i++) {
        int s = g_srcs[i];                               // broadcast load
        float ash = g_as1[s * H1 + head];
        float alpha = __expf(lrelu(ash + adh) - mh) * inv;
        const uint4* hp = reinterpret_cast<const uint4*>(g_h1h + (size_t)s * (D1 / 2));
        uint4 u = hp[lane];
        float2 f0 = __half22float2(*reinterpret_cast<__half2*>(&u.x));
        float2 f1 = __half22float2(*reinterpret_cast<__half2*>(&u.y));
        float2 f2 = __half22float2(*reinterpret_cast<__half2*>(&u.z));
        float2 f3 = __half22float2(*reinterpret_cast<__half2*>(&u.w));
        acc[0] += f0.x * alpha; acc[1] += f0.y * alpha;
        acc[2] += f1.x * alpha; acc[3] += f1.y * alpha;
        acc[4] += f2.x * alpha; acc[5] += f2.y * alpha;
        acc[6] += f3.x * alpha; acc[7] += f3.y * alpha;
    }

    int cb = lane * 8;
    float* op = g_acc1 + (size_t)w * D1 + cb;
    #pragma unroll
    for (int j = 0; j < 8; j++) {
        float v = acc[j] + b1[cb + j];
        op[j] = v > 0.f ? v : 0.f;
    }
}

// ---------------- fused layer2: online softmax + fp16 gather + bias -------
__global__ void gat2_fused_kernel(const float* __restrict__ b2,
                                  float* __restrict__ out) {
    int w = (blockIdx.x * blockDim.x + threadIdx.x) >> 5;
    int lane = threadIdx.x & 31;
    if (w >= NN) return;
    int beg = g_row[w], end = g_row[w + 1];

    float ad = g_ad2[w];

    float mxv = -INFINITY, smv = 0.f;
    for (int i = beg + lane; i < end; i += 32) {
        int s = g_srcs[i];
        float v = lrelu(g_as2[s] + ad);
        float nm = fmaxf(mxv, v);
        smv = smv * __expf(mxv - nm) + __expf(v - nm);
        mxv = nm;
    }
    #pragma unroll
    for (int o = 1; o < 32; o <<= 1) {
        float om = __shfl_xor_sync(0xFFFFFFFFu, mxv, o);
        float os = __shfl_xor_sync(0xFFFFFFFFu, smv, o);
        osm_combine(mxv, smv, om, os);
    }
    float inv = 1.f / (smv + 1e-16f);

    float a0 = 0.f, a1 = 0.f;
    #pragma unroll 4
    for (int i = beg; i < end; i++) {
        int s = g_srcs[i];
        float alpha = __expf(lrelu(g_as2[s] + ad) - mxv) * inv;
        __half2 hv = g_h2h[(size_t)s * (C2 / 2) + lane];
        float2 v = __half22float2(hv);
        a0 += v.x * alpha;
        a1 += v.y * alpha;
    }
    float* op = out + (size_t)w * C2 + 2 * lane;
    op[0] = a0 + b2[2 * lane];
    op[1] = a1 + b2[2 * lane + 1];
}

extern "C" void kernel_launch(void* const* d_in, const int* in_sizes, int n_in,
                              void* d_out, int out_size) {
    const float* x     = (const float*)d_in[0];
    const int*   ei    = (const int*)d_in[1];     // int32
    const float* W1    = (const float*)d_in[2];
    const float* at_s1 = (const float*)d_in[3];
    const float* at_d1 = (const float*)d_in[4];
    const float* b1    = (const float*)d_in[5];
    const float* W2    = (const float*)d_in[6];
    const float* at_s2 = (const float*)d_in[7];
    const float* at_d2 = (const float*)d_in[8];
    const float* b2    = (const float*)d_in[9];
    float* out = (float*)d_out;

    static float*   p_acc1 = nullptr;
    static __half2* p_h1h  = nullptr;
    static __half2* p_h2h  = nullptr;
    static float *p_as1, *p_ad1, *p_as2, *p_ad2;
    static cudaStream_t s_side = nullptr;
    static cudaEvent_t  ev_root = nullptr, ev_csr = nullptr;
    if (!p_acc1) {   // address lookup + stream/event creation (first call is
                     // the un-captured correctness run; no device mem alloc)
        cudaGetSymbolAddress((void**)&p_acc1, g_acc1);
        cudaGetSymbolAddress((void**)&p_h1h, g_h1h);
        cudaGetSymbolAddress((void**)&p_h2h, g_h2h);
        cudaGetSymbolAddress((void**)&p_as1, g_as1);
        cudaGetSymbolAddress((void**)&p_ad1, g_ad1);
        cudaGetSymbolAddress((void**)&p_as2, g_as2);
        cudaGetSymbolAddress((void**)&p_ad2, g_ad2);
        cudaStreamCreateWithFlags(&s_side, cudaStreamNonBlocking);
        cudaEventCreateWithFlags(&ev_root, cudaEventDisableTiming);
        cudaEventCreateWithFlags(&ev_csr, cudaEventDisableTiming);
    }

    // ---- fork: CSR build on side stream, overlapped with layer-1 GEMM ----
    // Host launch order keeps sgemm1 as the 4th launch (ncu -s 5 -c 1 window).
    cudaEventRecord(ev_root, (cudaStream_t)0);
    cudaStreamWaitEvent(s_side, ev_root, 0);
    zero_counts_kernel<<<(NN + 255) / 256, 256, 0, s_side>>>();   // #1
    hist_kernel<<<(ET + 255) / 256, 256, 0, s_side>>>(ei);        // #2
    scan_kernel<<<1, 1024, 0, s_side>>>();                        // #3

    // ---- layer 1 GEMM (main stream) ----                       // #4
    sgemm_fused_kernel<<<dim3(D1 / BN, (NN + BM - 1) / BM), 256>>>(
        x, W1, p_h1h, at_s1, at_d1, p_as1, p_ad1, NN, D1, IN1, H1);

    scatter_kernel<<<(ET + 255) / 256, 256, 0, s_side>>>(ei);     // #5
    cudaEventRecord(ev_csr, s_side);

    cudaStreamWaitEvent((cudaStream_t)0, ev_csr, 0);   // join CSR
    gat1_fused_kernel<<<(NN + 7) / 8, 256>>>(b1);                 // #6

    // ---- layer 2 ----
    sgemm_fused_kernel<<<dim3(C2 / BN, (NN + BM - 1) / BM), 256>>>(
        p_acc1, W2, p_h2h, at_s2, at_d2, p_as2, p_ad2, NN, C2, D1, 1);
    gat2_fused_kernel<<<(NN + 7) / 8, 256>>>(b2, out);
}

// round 14
// speedup vs baseline: 2.2795x; 1.2613x over previous
#include <cuda_runtime.h>
#include <cuda_fp16.h>
#include <math.h>

// Problem constants (fixed for this dataset)
#define NN 50000
#define EE 800000
#define ET (EE + NN)      // 850000 edges incl. self loops
#define H1 4
#define C1 64
#define D1 256            // H1*C1
#define C2 64
#define IN1 128
#define NEG_SLOPE 0.2f

// ---------------- scratch (device globals, no runtime alloc) ----------------
__device__ __half2 g_h1h[(size_t)NN * D1 / 2];   // fp16 h1 (gather source)
__device__ float   g_acc1[(size_t)NN * D1];      // layer1 output (post bias+relu)
__device__ float   g_as1[NN * H1];
__device__ float   g_ad1[NN * H1];
__device__ __half2 g_h2h[(size_t)NN * C2 / 2];
__device__ float   g_as2[NN];
__device__ float   g_ad2[NN];
// CSR by dst
__device__ int g_deg[NN];
__device__ int g_cur[NN];
__device__ int g_row[NN + 1];
__device__ int g_srcs[ET];

__device__ __forceinline__ float lrelu(float v) {
    return v > 0.f ? v : NEG_SLOPE * v;
}

// online-softmax combine: (m,s) <- (m,s) ⊕ (om,os); NaN-safe for -inf pairs
__device__ __forceinline__ void osm_combine(float& m, float& s, float om, float os) {
    float nm = fmaxf(m, om);
    s = s * __expf(fmaxf(m - nm, -88.f)) + os * __expf(fmaxf(om - nm, -88.f));
    m = nm;
}

__device__ __forceinline__ unsigned f2tf32(float f) {
    unsigned r;
    asm("cvt.rna.tf32.f32 %0, %1;" : "=r"(r) : "f"(f));
    return r;
}

__device__ __forceinline__ unsigned smem_u32(const void* p) {
    return (unsigned)__cvta_generic_to_shared(p);
}

__device__ __forceinline__ void cp16(unsigned dst, const float* src, bool pred) {
    asm volatile("cp.async.cg.shared.global [%0], [%1], 16, %2;"
                 :: "r"(dst), "l"(src), "r"(pred ? 16 : 0));
}

// ---------------- CSR build ----------------
__global__ void zero_counts_kernel() {
    int i = blockIdx.x * blockDim.x + threadIdx.x;
    if (i < NN) { g_deg[i] = 0; g_cur[i] = 0; }
}

__global__ void hist_kernel(const int* __restrict__ ei) {
    int e = blockIdx.x * blockDim.x + threadIdx.x;
    if (e >= ET) return;
    int d = (e < EE) ? ei[EE + e] : (e - EE);
    atomicAdd(&g_deg[d], 1);
}

// single-block exclusive scan of g_deg -> g_row  (1024 threads)
__global__ void scan_kernel() {
    __shared__ int warp_sums[32];
    const int CHUNK = (NN + 1023) / 1024;   // 49
    int t = threadIdx.x;
    int lane = t & 31, wid = t >> 5;
    int start = t * CHUNK;
    int local = 0;
    for (int i = 0; i < CHUNK; i++) {
        int idx = start + i;
        if (idx < NN) local += g_deg[idx];
    }
    int v = local;
    #pragma unroll
    for (int o = 1; o < 32; o <<= 1) {
        int n = __shfl_up_sync(0xFFFFFFFFu, v, o);
        if (lane >= o) v += n;
    }
    if (lane == 31) warp_sums[wid] = v;
    __syncthreads();
    if (wid == 0) {
        int w = warp_sums[lane];
        #pragma unroll
        for (int o = 1; o < 32; o <<= 1) {
            int n = __shfl_up_sync(0xFFFFFFFFu, w, o);
            if (lane >= o) w += n;
        }
        warp_sums[lane] = w;
    }
    __syncthreads();
    int excl = v - local + (wid > 0 ? warp_sums[wid - 1] : 0);
    int run = excl;
    for (int i = 0; i < CHUNK; i++) {
        int idx = start + i;
        if (idx < NN) {
            int dg = g_deg[idx];
            g_row[idx] = run;
            run += dg;
        }
    }
    if (t == 1023) g_row[NN] = run;   // == ET
}

__global__ void scatter_kernel(const int* __restrict__ ei) {
    int e = blockIdx.x * blockDim.x + threadIdx.x;
    if (e >= ET) return;
    int s, d;
    if (e < EE) { s = ei[e]; d = ei[EE + e]; } else { s = d = e - EE; }
    int pos = atomicAdd(&g_cur[d], 1);
    g_srcs[g_row[d] + pos] = s;
}

// ---------- tf32 tensor-core GEMM (cp.async pipeline) + fused epilogue ----
// C fp16 = A[M,K] @ B[K,N]; one head per BN=64 col block.
// 8 warps: wm = wid&3, wn = wid>>2; warp tile 32x32; mma.m16n8k8 tf32.
// Smem: natural layout with padding (A row 20 floats, B row 72 floats) ->
// conflict-free scalar fragment LDS. 3-stage cp.async pipeline.
#define BM 128
#define BN 64
#define BK 16
#define APAD 20
#define BPAD 72

__global__ __launch_bounds__(256, 2)
void sgemm_fused_kernel(const float* __restrict__ A,
                        const float* __restrict__ B,
                        __half2* __restrict__ Ch,
                        const float* __restrict__ att_s,
                        const float* __restrict__ att_d,
                        float* __restrict__ as_out,
                        float* __restrict__ ad_out,
                        int M, int N, int K, int Hs) {
    __shared__ float A_sm[3][BM][APAD];   // 30720 B
    __shared__ float B_sm[3][BK][BPAD];   // 13824 B
    __shared__ float red_s[2][BM];
    __shared__ float red_d[2][BM];

    const int tid  = threadIdx.x;
    const int lane = tid & 31;
    const int wid  = tid >> 5;
    const int wm   = wid & 3;          // warp m index (0..3)
    const int wn   = wid >> 2;         // warp n index (0..1)
    const int g    = lane >> 2;        // groupID
    const int t4   = lane & 3;         // threadID in group
    const int row0 = blockIdx.y * BM, col0 = blockIdx.x * BN;

    // cp.async mappings
    const int am  = tid >> 2;          // A row (0..63), second at +64
    const int ak  = (tid & 3) * 4;     // A k offset (16B chunk)
    const int bkr = tid >> 4;          // B k row (0..15)
    const int bn4 = (tid & 15) * 4;    // B n offset

    const int nk = K / BK;

    const bool p0 = (row0 + am) < M;
    const bool p1 = (row0 + am + 64) < M;
    const float* ga0_base = A + (size_t)(p0 ? row0 + am      : 0) * K + ak;
    const float* ga1_base = A + (size_t)(p1 ? row0 + am + 64 : 0) * K + ak;
    const float* gb_base  = B + (size_t)bkr * N + col0 + bn4;

    #define ISSUE(kt, bufi) do {                                              \
        int k0i = (kt) * BK;                                                  \
        cp16(smem_u32(&A_sm[bufi][am][ak]),      ga0_base + k0i, p0);         \
        cp16(smem_u32(&A_sm[bufi][am + 64][ak]), ga1_base + k0i, p1);         \
        cp16(smem_u32(&B_sm[bufi][bkr][bn4]),    gb_base + (size_t)k0i * N, true); \
        asm volatile("cp.async.commit_group;");                               \
    } while (0)

    ISSUE(0, 0);
    if (nk > 1) ISSUE(1, 1);

    float acc[2][4][4] = {};
    for (int kt = 0; kt < nk; kt++) {
        // drain: group kt must be complete before reading its buffer.
        // While another group is still committed behind it we can leave 1
        // in flight; on the LAST tile group kt IS the newest -> wait 0.
        if (kt + 1 < nk) asm volatile("cp.async.wait_group 1;");
        else             asm volatile("cp.async.wait_group 0;");
        __syncthreads();
        if (kt + 2 < nk) ISSUE(kt + 2, (kt + 2) % 3);
        const int buf = kt % 3;
        #pragma unroll
        for (int kc = 0; kc < 2; kc++) {
            const int k0 = kc * 8;
            unsigned af[2][4];
            #pragma unroll
            for (int mtl = 0; mtl < 2; mtl++) {
                int mb = wm * 32 + mtl * 16;
                af[mtl][0] = f2tf32(A_sm[buf][mb + g][k0 + t4]);
                af[mtl][1] = f2tf32(A_sm[buf][mb + 8 + g][k0 + t4]);
                af[mtl][2] = f2tf32(A_sm[buf][mb + g][k0 + t4 + 4]);
                af[mtl][3] = f2tf32(A_sm[buf][mb + 8 + g][k0 + t4 + 4]);
            }
            unsigned bf[4][2];
            #pragma unroll
            for (int ntl = 0; ntl < 4; ntl++) {
                int nb = wn * 32 + ntl * 8;
                bf[ntl][0] = f2tf32(B_sm[buf][k0 + t4][nb + g]);
                bf[ntl][1] = f2tf32(B_sm[buf][k0 + t4 + 4][nb + g]);
            }
            #pragma unroll
            for (int mtl = 0; mtl < 2; mtl++)
                #pragma unroll
                for (int ntl = 0; ntl < 4; ntl++)
                    asm volatile(
                        "mma.sync.aligned.m16n8k8.row.col.f32.tf32.tf32.f32 "
                        "{%0,%1,%2,%3}, {%4,%5,%6,%7}, {%8,%9}, {%0,%1,%2,%3};"
                        : "+f"(acc[mtl][ntl][0]), "+f"(acc[mtl][ntl][1]),
                          "+f"(acc[mtl][ntl][2]), "+f"(acc[mtl][ntl][3])
                        : "r"(af[mtl][0]), "r"(af[mtl][1]), "r"(af[mtl][2]), "r"(af[mtl][3]),
                          "r"(bf[ntl][0]), "r"(bf[ntl][1]));
        }
        __syncthreads();
    }
    #undef ISSUE

    // ---- epilogue: fp16 store + per-warp attention partial dots ----
    float ps[2][2] = {}, pd[2][2] = {};
    #pragma unroll
    for (int mtl = 0; mtl < 2; mtl++) {
        int rlo = row0 + wm * 32 + mtl * 16 + g;
        int rhi = rlo + 8;
        #pragma unroll
        for (int ntl = 0; ntl < 4; ntl++) {
            int cn = wn * 32 + ntl * 8 + 2 * t4;     // col within this N block
            float a0 = acc[mtl][ntl][0], a1 = acc[mtl][ntl][1];
            float a2 = acc[mtl][ntl][2], a3 = acc[mtl][ntl][3];
            if (rlo < M)
                Ch[((size_t)rlo * N + col0 + cn) / 2] = __floats2half2_rn(a0, a1);
            if (rhi < M)
                Ch[((size_t)rhi * N + col0 + cn) / 2] = __floats2half2_rn(a2, a3);
            float s0 = att_s[col0 + cn], s1 = att_s[col0 + cn + 1];
            float d0 = att_d[col0 + cn], d1 = att_d[col0 + cn + 1];
            ps[mtl][0] += a0 * s0 + a1 * s1;  pd[mtl][0] += a0 * d0 + a1 * d1;
            ps[mtl][1] += a2 * s0 + a3 * s1;  pd[mtl][1] += a2 * d0 + a3 * d1;
        }
        // reduce across the 4 lanes sharing each row (t4 group)
        #pragma unroll
        for (int o = 1; o < 4; o <<= 1) {
            ps[mtl][0] += __shfl_xor_sync(0xFFFFFFFFu, ps[mtl][0], o);
            ps[mtl][1] += __shfl_xor_sync(0xFFFFFFFFu, ps[mtl][1], o);
            pd[mtl][0] += __shfl_xor_sync(0xFFFFFFFFu, pd[mtl][0], o);
            pd[mtl][1] += __shfl_xor_sync(0xFFFFFFFFu, pd[mtl][1], o);
        }
        if (t4 == 0) {
            int rloc = wm * 32 + mtl * 16 + g;
            red_s[wn][rloc]     = ps[mtl][0];
            red_s[wn][rloc + 8] = ps[mtl][1];
            red_d[wn][rloc]     = pd[mtl][0];
            red_d[wn][rloc + 8] = pd[mtl][1];
        }
    }
    __syncthreads();
    if (tid < BM) {
        int r = row0 + tid;
        if (r < M) {
            as_out[r * Hs + blockIdx.x] = red_s[0][tid] + red_s[1][tid];
            ad_out[r * Hs + blockIdx.x] = red_d[0][tid] + red_d[1][tid];
        }
    }
}

// ---------------- fused layer1: online softmax + fp16 gather + bias + relu
// one warp per dst node; lane covers 8 cols (head = lane>>3)
__global__ void gat1_fused_kernel(const float* __restrict__ b1) {
    int w = (blockIdx.x * blockDim.x + threadIdx.x) >> 5;
    int lane = threadIdx.x & 31;
    if (w >= NN) return;
    int beg = g_row[w], end = g_row[w + 1];

    float4 adv = *reinterpret_cast<const float4*>(g_ad1 + w * H1);

    // single pass: online softmax (per-lane running max + rescaled sum)
    float4 mx = make_float4(-INFINITY, -INFINITY, -INFINITY, -INFINITY);
    float4 sm = make_float4(0.f, 0.f, 0.f, 0.f);
    for (int i = beg + lane; i < end; i += 32) {
        int s = g_srcs[i];
        float4 a = *reinterpret_cast<const float4*>(g_as1 + s * H1);
        float vx = lrelu(a.x + adv.x), vy = lrelu(a.y + adv.y);
        float vz = lrelu(a.z + adv.z), vw = lrelu(a.w + adv.w);
        float nx = fmaxf(mx.x, vx), ny = fmaxf(mx.y, vy);
        float nz = fmaxf(mx.z, vz), nw = fmaxf(mx.w, vw);
        sm.x = sm.x * __expf(mx.x - nx) + __expf(vx - nx);
        sm.y = sm.y * __expf(mx.y - ny) + __expf(vy - ny);
        sm.z = sm.z * __expf(mx.z - nz) + __expf(vz - nz);
        sm.w = sm.w * __expf(mx.w - nw) + __expf(vw - nw);
        mx.x = nx; mx.y = ny; mx.z = nz; mx.w = nw;
    }
    // lane combine
    #pragma unroll
    for (int o = 1; o < 32; o <<= 1) {
        float omx, osx;
        omx = __shfl_xor_sync(0xFFFFFFFFu, mx.x, o);
        osx = __shfl_xor_sync(0xFFFFFFFFu, sm.x, o);
        osm_combine(mx.x, sm.x, omx, osx);
        omx = __shfl_xor_sync(0xFFFFFFFFu, mx.y, o);
        osx = __shfl_xor_sync(0xFFFFFFFFu, sm.y, o);
        osm_combine(mx.y, sm.y, omx, osx);
        omx = __shfl_xor_sync(0xFFFFFFFFu, mx.z, o);
        osx = __shfl_xor_sync(0xFFFFFFFFu, sm.z, o);
        osm_combine(mx.z, sm.z, omx, osx);
        omx = __shfl_xor_sync(0xFFFFFFFFu, mx.w, o);
        osx = __shfl_xor_sync(0xFFFFFFFFu, sm.w, o);
        osm_combine(mx.w, sm.w, omx, osx);
    }

    int head = lane >> 3;
    float mh  = (head == 0) ? mx.x : (head == 1) ? mx.y : (head == 2) ? mx.z : mx.w;
    float shv = (head == 0) ? sm.x : (head == 1) ? sm.y : (head == 2) ? sm.z : sm.w;
    float adh = (head == 0) ? adv.x : (head == 1) ? adv.y : (head == 2) ? adv.z : adv.w;
    float inv = 1.f / (shv + 1e-16f);

    // pass C: direct per-edge gather + fp32 accumulate (warp-uniform broadcast)
    float acc[8] = {};
    #pragma unroll 4
    for (int i = beg; i < end; i++) {
        int s = g_srcs[i];                               // broadcast load
        float ash = g_as1[s * H1 + head];
        float alpha = __expf(lrelu(ash + adh) - mh) * inv;
        const uint4* hp = reinterpret_cast<const uint4*>(g_h1h + (size_t)s * (D1 / 2));
        uint4 u = hp[lane];
        float2 f0 = __half22float2(*reinterpret_cast<__half2*>(&u.x));
        float2 f1 = __half22float2(*reinterpret_cast<__half2*>(&u.y));
        float2 f2 = __half22float2(*reinterpret_cast<__half2*>(&u.z));
        float2 f3 = __half22float2(*reinterpret_cast<__half2*>(&u.w));
        acc[0] += f0.x * alpha; acc[1] += f0.y * alpha;
        acc[2] += f1.x * alpha; acc[3] += f1.y * alpha;
        acc[4] += f2.x * alpha; acc[5] += f2.y * alpha;
        acc[6] += f3.x * alpha; acc[7] += f3.y * alpha;
    }

    int cb = lane * 8;
    float* op = g_acc1 + (size_t)w * D1 + cb;
    #pragma unroll
    for (int j = 0; j < 8; j++) {
        float v = acc[j] + b1[cb + j];
        op[j] = v > 0.f ? v : 0.f;
    }
}

// ---------------- fused layer2: online softmax + fp16 gather + bias -------
__global__ void gat2_fused_kernel(const float* __restrict__ b2,
                                  float* __restrict__ out) {
    int w = (blockIdx.x * blockDim.x + threadIdx.x) >> 5;
    int lane = threadIdx.x & 31;
    if (w >= NN) return;
    int beg = g_row[w], end = g_row[w + 1];

    float ad = g_ad2[w];

    float mxv = -INFINITY, smv = 0.f;
    for (int i = beg + lane; i < end; i += 32) {
        int s = g_srcs[i];
        float v = lrelu(g_as2[s] + ad);
        float nm = fmaxf(mxv, v);
        smv = smv * __expf(mxv - nm) + __expf(v - nm);
        mxv = nm;
    }
    #pragma unroll
    for (int o = 1; o < 32; o <<= 1) {
        float om = __shfl_xor_sync(0xFFFFFFFFu, mxv, o);
        float os = __shfl_xor_sync(0xFFFFFFFFu, smv, o);
        osm_combine(mxv, smv, om, os);
    }
    float inv = 1.f / (smv + 1e-16f);

    float a0 = 0.f, a1 = 0.f;
    #pragma unroll 4
    for (int i = beg; i < end; i++) {
        int s = g_srcs[i];
        float alpha = __expf(lrelu(g_as2[s] + ad) - mxv) * inv;
        __half2 hv = g_h2h[(size_t)s * (C2 / 2) + lane];
        float2 v = __half22float2(hv);
        a0 += v.x * alpha;
        a1 += v.y * alpha;
    }
    float* op = out + (size_t)w * C2 + 2 * lane;
    op[0] = a0 + b2[2 * lane];
    op[1] = a1 + b2[2 * lane + 1];
}

extern "C" void kernel_launch(void* const* d_in, const int* in_sizes, int n_in,
                              void* d_out, int out_size) {
    const float* x     = (const float*)d_in[0];
    const int*   ei    = (const int*)d_in[1];     // int32
    const float* W1    = (const float*)d_in[2];
    const float* at_s1 = (const float*)d_in[3];
    const float* at_d1 = (const float*)d_in[4];
    const float* b1    = (const float*)d_in[5];
    const float* W2    = (const float*)d_in[6];
    const float* at_s2 = (const float*)d_in[7];
    const float* at_d2 = (const float*)d_in[8];
    const float* b2    = (const float*)d_in[9];
    float* out = (float*)d_out;

    static float*   p_acc1 = nullptr;
    static __half2* p_h1h  = nullptr;
    static __half2* p_h2h  = nullptr;
    static float *p_as1, *p_ad1, *p_as2, *p_ad2;
    static cudaStream_t s_side = nullptr;
    static cudaEvent_t  ev_root = nullptr, ev_csr = nullptr;
    if (!p_acc1) {   // address lookup + stream/event creation (first call is
                     // the un-captured correctness run; no device mem alloc)
        cudaGetSymbolAddress((void**)&p_acc1, g_acc1);
        cudaGetSymbolAddress((void**)&p_h1h, g_h1h);
        cudaGetSymbolAddress((void**)&p_h2h, g_h2h);
        cudaGetSymbolAddress((void**)&p_as1, g_as1);
        cudaGetSymbolAddress((void**)&p_ad1, g_ad1);
        cudaGetSymbolAddress((void**)&p_as2, g_as2);
        cudaGetSymbolAddress((void**)&p_ad2, g_ad2);
        cudaStreamCreateWithFlags(&s_side, cudaStreamNonBlocking);
        cudaEventCreateWithFlags(&ev_root, cudaEventDisableTiming);
        cudaEventCreateWithFlags(&ev_csr, cudaEventDisableTiming);
    }

    // ---- fork: CSR build on side stream, overlapped with layer-1 GEMM ----
    // Host launch order keeps sgemm1 as the 4th launch (ncu -s 5 -c 1 window).
    cudaEventRecord(ev_root, (cudaStream_t)0);
    cudaStreamWaitEvent(s_side, ev_root, 0);
    zero_counts_kernel<<<(NN + 255) / 256, 256, 0, s_side>>>();   // #1
    hist_kernel<<<(ET + 255) / 256, 256, 0, s_side>>>(ei);        // #2
    scan_kernel<<<1, 1024, 0, s_side>>>();                        // #3

    // ---- layer 1 GEMM (main stream) ----                       // #4
    sgemm_fused_kernel<<<dim3(D1 / BN, (NN + BM - 1) / BM), 256>>>(
        x, W1, p_h1h, at_s1, at_d1, p_as1, p_ad1, NN, D1, IN1, H1);

    scatter_kernel<<<(ET + 255) / 256, 256, 0, s_side>>>(ei);     // #5
    cudaEventRecord(ev_csr, s_side);

    cudaStreamWaitEvent((cudaStream_t)0, ev_csr, 0);   // join CSR
    gat1_fused_kernel<<<(NN + 7) / 8, 256>>>(b1);                 // #6

    // ---- layer 2 ----
    sgemm_fused_kernel<<<dim3(C2 / BN, (NN + BM - 1) / BM), 256>>>(
        p_acc1, W2, p_h2h, at_s2, at_d2, p_as2, p_ad2, NN, C2, D1, 1);
    gat2_fused_kernel<<<(NN + 7) / 8, 256>>>(b2, out);
}

// round 15
// speedup vs baseline: 2.5638x; 1.1247x over previous
#include <cuda_runtime.h>
#include <cuda_fp16.h>
#include <math.h>

// Problem constants (fixed for this dataset)
#define NN 50000
#define EE 800000
#define ET (EE + NN)      // 850000 edges incl. self loops
#define H1 4
#define C1 64
#define D1 256            // H1*C1
#define C2 64
#define IN1 128
#define NEG_SLOPE 0.2f

// ---------------- scratch (device globals, no runtime alloc) ----------------
__device__ __half2 g_h1h[(size_t)NN * D1 / 2];   // fp16 h1 (gather source)
__device__ float   g_acc1[(size_t)NN * D1];      // layer1 output (post bias+relu)
__device__ float   g_as1[NN * H1];
__device__ float   g_ad1[NN * H1];
__device__ __half2 g_h2h[(size_t)NN * C2 / 2];
__device__ float   g_as2[NN];
__device__ float   g_ad2[NN];
// CSR by dst
__device__ int g_deg[NN];      // hist counters; reset by scatter for next call
__device__ int g_cur[NN];      // running write pointers (init by scan to row[d])
__device__ int g_row[NN + 1];
__device__ int g_srcs[ET];

__device__ __forceinline__ float lrelu(float v) {
    return v > 0.f ? v : NEG_SLOPE * v;
}

// online-softmax combine: (m,s) <- (m,s) ⊕ (om,os); NaN-safe for -inf pairs
__device__ __forceinline__ void osm_combine(float& m, float& s, float om, float os) {
    float nm = fmaxf(m, om);
    s = s * __expf(fmaxf(m - nm, -88.f)) + os * __expf(fmaxf(om - nm, -88.f));
    m = nm;
}

__device__ __forceinline__ unsigned f2tf32(float f) {
    unsigned r;
    asm("cvt.rna.tf32.f32 %0, %1;" : "=r"(r) : "f"(f));
    return r;
}

__device__ __forceinline__ unsigned smem_u32(const void* p) {
    return (unsigned)__cvta_generic_to_shared(p);
}

__device__ __forceinline__ void cp16(unsigned dst, const float* src, bool pred) {
    asm volatile("cp.async.cg.shared.global [%0], [%1], 16, %2;"
                 :: "r"(dst), "l"(src), "r"(pred ? 16 : 0));
}

// ---------------- CSR build ----------------
__global__ void hist_kernel(const int* __restrict__ ei) {
    int e = blockIdx.x * blockDim.x + threadIdx.x;
    if (e >= ET) return;
    int d = (e < EE) ? ei[EE + e] : (e - EE);
    atomicAdd(&g_deg[d], 1);
}

// strip-mined coalesced exclusive scan: g_deg -> g_row (+ g_cur = row)
// 1 block, 1024 threads, 49 strips of 1024 contiguous elements.
__global__ void scan_kernel() {
    __shared__ int wsum[32];
    int t = threadIdx.x, lane = t & 31, wid = t >> 5;
    int base = 0;
    for (int strip = 0; strip < NN; strip += 1024) {
        int idx = strip + t;
        int orig = (idx < NN) ? g_deg[idx] : 0;
        int v = orig;
        #pragma unroll
        for (int o = 1; o < 32; o <<= 1) {
            int n = __shfl_up_sync(0xFFFFFFFFu, v, o);
            if (lane >= o) v += n;
        }
        if (lane == 31) wsum[wid] = v;
        __syncthreads();
        // every warp redundantly scans the 32 warp totals (no 2nd barrier)
        int w = wsum[lane];
        #pragma unroll
        for (int o = 1; o < 32; o <<= 1) {
            int n = __shfl_up_sync(0xFFFFFFFFu, w, o);
            if (lane >= o) w += n;
        }
        int wpre  = __shfl_sync(0xFFFFFFFFu, w, (wid + 31) & 31);
        if (wid == 0) wpre = 0;
        int total = __shfl_sync(0xFFFFFFFFu, w, 31);
        int excl = base + wpre + (v - orig);
        if (idx < NN) { g_row[idx] = excl; g_cur[idx] = excl; }
        base += total;
        __syncthreads();   // protect wsum before next strip overwrites
    }
    if (t == 0) g_row[NN] = base;   // == ET
}

__global__ void scatter_kernel(const int* __restrict__ ei) {
    int e = blockIdx.x * blockDim.x + threadIdx.x;
    if (e < NN) g_deg[e] = 0;       // reset hist counters for the next call
    if (e >= ET) return;
    int s, d;
    if (e < EE) { s = ei[e]; d = ei[EE + e]; } else { s = d = e - EE; }
    int pos = atomicAdd(&g_cur[d], 1);
    g_srcs[pos] = s;
}

// ---------- tf32 tensor-core GEMM (cp.async pipeline) + fused epilogue ----
// C fp16 = A[M,K] @ B[K,N]; one head per BN=64 col block.
// 8 warps: wm = wid&3, wn = wid>>2; warp tile 32x32; mma.m16n8k8 tf32.
#define BM 128
#define BN 64
#define BK 16
#define APAD 20
#define BPAD 72

__global__ __launch_bounds__(256, 2)
void sgemm_fused_kernel(const float* __restrict__ A,
                        const float* __restrict__ B,
                        __half2* __restrict__ Ch,
                        const float* __restrict__ att_s,
                        const float* __restrict__ att_d,
                        float* __restrict__ as_out,
                        float* __restrict__ ad_out,
                        int M, int N, int K, int Hs) {
    __shared__ float A_sm[3][BM][APAD];   // 30720 B
    __shared__ float B_sm[3][BK][BPAD];   // 13824 B
    __shared__ float red_s[2][BM];
    __shared__ float red_d[2][BM];

    const int tid  = threadIdx.x;
    const int lane = tid & 31;
    const int wid  = tid >> 5;
    const int wm   = wid & 3;          // warp m index (0..3)
    const int wn   = wid >> 2;         // warp n index (0..1)
    const int g    = lane >> 2;        // groupID
    const int t4   = lane & 3;         // threadID in group
    const int row0 = blockIdx.y * BM, col0 = blockIdx.x * BN;

    // cp.async mappings
    const int am  = tid >> 2;          // A row (0..63), second at +64
    const int ak  = (tid & 3) * 4;     // A k offset (16B chunk)
    const int bkr = tid >> 4;          // B k row (0..15)
    const int bn4 = (tid & 15) * 4;    // B n offset

    const int nk = K / BK;

    const bool p0 = (row0 + am) < M;
    const bool p1 = (row0 + am + 64) < M;
    const float* ga0_base = A + (size_t)(p0 ? row0 + am      : 0) * K + ak;
    const float* ga1_base = A + (size_t)(p1 ? row0 + am + 64 : 0) * K + ak;
    const float* gb_base  = B + (size_t)bkr * N + col0 + bn4;

    #define ISSUE(kt, bufi) do {                                              \
        int k0i = (kt) * BK;                                                  \
        cp16(smem_u32(&A_sm[bufi][am][ak]),      ga0_base + k0i, p0);         \
        cp16(smem_u32(&A_sm[bufi][am + 64][ak]), ga1_base + k0i, p1);         \
        cp16(smem_u32(&B_sm[bufi][bkr][bn4]),    gb_base + (size_t)k0i * N, true); \
        asm volatile("cp.async.commit_group;");                               \
    } while (0)

    ISSUE(0, 0);
    if (nk > 1) ISSUE(1, 1);

    float acc[2][4][4] = {};
    for (int kt = 0; kt < nk; kt++) {
        // drain: group kt must be complete before reading its buffer.
        if (kt + 1 < nk) asm volatile("cp.async.wait_group 1;");
        else             asm volatile("cp.async.wait_group 0;");
        __syncthreads();
        if (kt + 2 < nk) ISSUE(kt + 2, (kt + 2) % 3);
        const int buf = kt % 3;
        #pragma unroll
        for (int kc = 0; kc < 2; kc++) {
            const int k0 = kc * 8;
            unsigned af[2][4];
            #pragma unroll
            for (int mtl = 0; mtl < 2; mtl++) {
                int mb = wm * 32 + mtl * 16;
                af[mtl][0] = f2tf32(A_sm[buf][mb + g][k0 + t4]);
                af[mtl][1] = f2tf32(A_sm[buf][mb + 8 + g][k0 + t4]);
                af[mtl][2] = f2tf32(A_sm[buf][mb + g][k0 + t4 + 4]);
                af[mtl][3] = f2tf32(A_sm[buf][mb + 8 + g][k0 + t4 + 4]);
            }
            unsigned bf[4][2];
            #pragma unroll
            for (int ntl = 0; ntl < 4; ntl++) {
                int nb = wn * 32 + ntl * 8;
                bf[ntl][0] = f2tf32(B_sm[buf][k0 + t4][nb + g]);
                bf[ntl][1] = f2tf32(B_sm[buf][k0 + t4 + 4][nb + g]);
            }
            #pragma unroll
            for (int mtl = 0; mtl < 2; mtl++)
                #pragma unroll
                for (int ntl = 0; ntl < 4; ntl++)
                    asm volatile(
                        "mma.sync.aligned.m16n8k8.row.col.f32.tf32.tf32.f32 "
                        "{%0,%1,%2,%3}, {%4,%5,%6,%7}, {%8,%9}, {%0,%1,%2,%3};"
                        : "+f"(acc[mtl][ntl][0]), "+f"(acc[mtl][ntl][1]),
                          "+f"(acc[mtl][ntl][2]), "+f"(acc[mtl][ntl][3])
                        : "r"(af[mtl][0]), "r"(af[mtl][1]), "r"(af[mtl][2]), "r"(af[mtl][3]),
                          "r"(bf[ntl][0]), "r"(bf[ntl][1]));
        }
        __syncthreads();
    }
    #undef ISSUE

    // ---- epilogue: fp16 store + per-warp attention partial dots ----
    float ps[2][2] = {}, pd[2][2] = {};
    #pragma unroll
    for (int mtl = 0; mtl < 2; mtl++) {
        int rlo = row0 + wm * 32 + mtl * 16 + g;
        int rhi = rlo + 8;
        #pragma unroll
        for (int ntl = 0; ntl < 4; ntl++) {
            int cn = wn * 32 + ntl * 8 + 2 * t4;     // col within this N block
            float a0 = acc[mtl][ntl][0], a1 = acc[mtl][ntl][1];
            float a2 = acc[mtl][ntl][2], a3 = acc[mtl][ntl][3];
            if (rlo < M)
                Ch[((size_t)rlo * N + col0 + cn) / 2] = __floats2half2_rn(a0, a1);
            if (rhi < M)
                Ch[((size_t)rhi * N + col0 + cn) / 2] = __floats2half2_rn(a2, a3);
            float s0 = att_s[col0 + cn], s1 = att_s[col0 + cn + 1];
            float d0 = att_d[col0 + cn], d1 = att_d[col0 + cn + 1];
            ps[mtl][0] += a0 * s0 + a1 * s1;  pd[mtl][0] += a0 * d0 + a1 * d1;
            ps[mtl][1] += a2 * s0 + a3 * s1;  pd[mtl][1] += a2 * d0 + a3 * d1;
        }
        // reduce across the 4 lanes sharing each row (t4 group)
        #pragma unroll
        for (int o = 1; o < 4; o <<= 1) {
            ps[mtl][0] += __shfl_xor_sync(0xFFFFFFFFu, ps[mtl][0], o);
            ps[mtl][1] += __shfl_xor_sync(0xFFFFFFFFu, ps[mtl][1], o);
            pd[mtl][0] += __shfl_xor_sync(0xFFFFFFFFu, pd[mtl][0], o);
            pd[mtl][1] += __shfl_xor_sync(0xFFFFFFFFu, pd[mtl][1], o);
        }
        if (t4 == 0) {
            int rloc = wm * 32 + mtl * 16 + g;
            red_s[wn][rloc]     = ps[mtl][0];
            red_s[wn][rloc + 8] = ps[mtl][1];
            red_d[wn][rloc]     = pd[mtl][0];
            red_d[wn][rloc + 8] = pd[mtl][1];
        }
    }
    __syncthreads();
    if (tid < BM) {
        int r = row0 + tid;
        if (r < M) {
            as_out[r * Hs + blockIdx.x] = red_s[0][tid] + red_s[1][tid];
            ad_out[r * Hs + blockIdx.x] = red_d[0][tid] + red_d[1][tid];
        }
    }
}

// ---------------- fused layer1: online softmax + fp16 gather + bias + relu
// one warp per dst node; lane covers 8 cols (head = lane>>3)
__global__ void gat1_fused_kernel(const float* __restrict__ b1) {
    int w = (blockIdx.x * blockDim.x + threadIdx.x) >> 5;
    int lane = threadIdx.x & 31;
    if (w >= NN) return;
    int beg = g_row[w], end = g_row[w + 1];

    float4 adv = *reinterpret_cast<const float4*>(g_ad1 + w * H1);

    // single pass: online softmax (per-lane running max + rescaled sum)
    float4 mx = make_float4(-INFINITY, -INFINITY, -INFINITY, -INFINITY);
    float4 sm = make_float4(0.f, 0.f, 0.f, 0.f);
    for (int i = beg + lane; i < end; i += 32) {
        int s = g_srcs[i];
        float4 a = *reinterpret_cast<const float4*>(g_as1 + s * H1);
        float vx = lrelu(a.x + adv.x), vy = lrelu(a.y + adv.y);
        float vz = lrelu(a.z + adv.z), vw = lrelu(a.w + adv.w);
        float nx = fmaxf(mx.x, vx), ny = fmaxf(mx.y, vy);
        float nz = fmaxf(mx.z, vz), nw = fmaxf(mx.w, vw);
        sm.x = sm.x * __expf(mx.x - nx) + __expf(vx - nx);
        sm.y = sm.y * __expf(mx.y - ny) + __expf(vy - ny);
        sm.z = sm.z * __expf(mx.z - nz) + __expf(vz - nz);
        sm.w = sm.w * __expf(mx.w - nw) + __expf(vw - nw);
        mx.x = nx; mx.y = ny; mx.z = nz; mx.w = nw;
    }
    // lane combine
    #pragma unroll
    for (int o = 1; o < 32; o <<= 1) {
        float omx, osx;
        omx = __shfl_xor_sync(0xFFFFFFFFu, mx.x, o);
        osx = __shfl_xor_sync(0xFFFFFFFFu, sm.x, o);
        osm_combine(mx.x, sm.x, omx, osx);
        omx = __shfl_xor_sync(0xFFFFFFFFu, mx.y, o);
        osx = __shfl_xor_sync(0xFFFFFFFFu, sm.y, o);
        osm_combine(mx.y, sm.y, omx, osx);
        omx = __shfl_xor_sync(0xFFFFFFFFu, mx.z, o);
        osx = __shfl_xor_sync(0xFFFFFFFFu, sm.z, o);
        osm_combine(mx.z, sm.z, omx, osx);
        omx = __shfl_xor_sync(0xFFFFFFFFu, mx.w, o);
        osx = __shfl_xor_sync(0xFFFFFFFFu, sm.w, o);
        osm_combine(mx.w, sm.w, omx, osx);
    }

    int head = lane >> 3;
    float mh  = (head == 0) ? mx.x : (head == 1) ? mx.y : (head == 2) ? mx.z : mx.w;
    float shv = (head == 0) ? sm.x : (head == 1) ? sm.y : (head == 2) ? sm.z : sm.w;
    float adh = (head == 0) ? adv.x : (head == 1) ? adv.y : (head == 2) ? adv.z : adv.w;
    float inv = 1.f / (shv + 1e-16f);

    // pass C: direct per-edge gather + fp32 accumulate (warp-uniform broadcast)
    float acc[8] = {};
    #pragma unroll 4
    for (int i = beg; i < end; i++) {
        int s = g_srcs[i];                               // broadcast load
        float ash = g_as1[s * H1 + head];
        float alpha = __expf(lrelu(ash + adh) - mh) * inv;
        const uint4* hp = reinterpret_cast<const uint4*>(g_h1h + (size_t)s * (D1 / 2));
        uint4 u = hp[lane];
        float2 f0 = __half22float2(*reinterpret_cast<__half2*>(&u.x));
        float2 f1 = __half22float2(*reinterpret_cast<__half2*>(&u.y));
        float2 f2 = __half22float2(*reinterpret_cast<__half2*>(&u.z));
        float2 f3 = __half22float2(*reinterpret_cast<__half2*>(&u.w));
        acc[0] += f0.x * alpha; acc[1] += f0.y * alpha;
        acc[2] += f1.x * alpha; acc[3] += f1.y * alpha;
        acc[4] += f2.x * alpha; acc[5] += f2.y * alpha;
        acc[6] += f3.x * alpha; acc[7] += f3.y * alpha;
    }

    int cb = lane * 8;
    float* op = g_acc1 + (size_t)w * D1 + cb;
    #pragma unroll
    for (int j = 0; j < 8; j++) {
        float v = acc[j] + b1[cb + j];
        op[j] = v > 0.f ? v : 0.f;
    }
}

// ---------------- fused layer2: online softmax + fp16 gather + bias -------
__global__ void gat2_fused_kernel(const float* __restrict__ b2,
                                  float* __restrict__ out) {
    int w = (blockIdx.x * blockDim.x + threadIdx.x) >> 5;
    int lane = threadIdx.x & 31;
    if (w >= NN) return;
    int beg = g_row[w], end = g_row[w + 1];

    float ad = g_ad2[w];

    float mxv = -INFINITY, smv = 0.f;
    for (int i = beg + lane; i < end; i += 32) {
        int s = g_srcs[i];
        float v = lrelu(g_as2[s] + ad);
        float nm = fmaxf(mxv, v);
        smv = smv * __expf(mxv - nm) + __expf(v - nm);
        mxv = nm;
    }
    #pragma unroll
    for (int o = 1; o < 32; o <<= 1) {
        float om = __shfl_xor_sync(0xFFFFFFFFu, mxv, o);
        float os = __shfl_xor_sync(0xFFFFFFFFu, smv, o);
        osm_combine(mxv, smv, om, os);
    }
    float inv = 1.f / (smv + 1e-16f);

    float a0 = 0.f, a1 = 0.f;
    #pragma unroll 4
    for (int i = beg; i < end; i++) {
        int s = g_srcs[i];
        float alpha = __expf(lrelu(g_as2[s] + ad) - mxv) * inv;
        __half2 hv = g_h2h[(size_t)s * (C2 / 2) + lane];
        float2 v = __half22float2(hv);
        a0 += v.x * alpha;
        a1 += v.y * alpha;
    }
    float* op = out + (size_t)w * C2 + 2 * lane;
    op[0] = a0 + b2[2 * lane];
    op[1] = a1 + b2[2 * lane + 1];
}

extern "C" void kernel_launch(void* const* d_in, const int* in_sizes, int n_in,
                              void* d_out, int out_size) {
    const float* x     = (const float*)d_in[0];
    const int*   ei    = (const int*)d_in[1];     // int32
    const float* W1    = (const float*)d_in[2];
    const float* at_s1 = (const float*)d_in[3];
    const float* at_d1 = (const float*)d_in[4];
    const float* b1    = (const float*)d_in[5];
    const float* W2    = (const float*)d_in[6];
    const float* at_s2 = (const float*)d_in[7];
    const float* at_d2 = (const float*)d_in[8];
    const float* b2    = (const float*)d_in[9];
    float* out = (float*)d_out;

    static float*   p_acc1 = nullptr;
    static __half2* p_h1h  = nullptr;
    static __half2* p_h2h  = nullptr;
    static float *p_as1, *p_ad1, *p_as2, *p_ad2;
    static cudaStream_t s_side = nullptr;
    static cudaEvent_t  ev_root = nullptr, ev_csr = nullptr;
    if (!p_acc1) {   // address lookup + stream/event creation (first call is
                     // the un-captured correctness run; no device mem alloc)
        cudaGetSymbolAddress((void**)&p_acc1, g_acc1);
        cudaGetSymbolAddress((void**)&p_h1h, g_h1h);
        cudaGetSymbolAddress((void**)&p_h2h, g_h2h);
        cudaGetSymbolAddress((void**)&p_as1, g_as1);
        cudaGetSymbolAddress((void**)&p_ad1, g_ad1);
        cudaGetSymbolAddress((void**)&p_as2, g_as2);
        cudaGetSymbolAddress((void**)&p_ad2, g_ad2);
        cudaStreamCreateWithFlags(&s_side, cudaStreamNonBlocking);
        cudaEventCreateWithFlags(&ev_root, cudaEventDisableTiming);
        cudaEventCreateWithFlags(&ev_csr, cudaEventDisableTiming);
    }

    // ---- fork: CSR build on side stream, overlapped with layer-1 GEMM ----
    // (zero kernel eliminated: scan seeds g_cur with row offsets; scatter
    //  resets g_deg for the next call. Device globals start zero-initialized.)
    cudaEventRecord(ev_root, (cudaStream_t)0);
    cudaStreamWaitEvent(s_side, ev_root, 0);
    hist_kernel<<<(ET + 255) / 256, 256, 0, s_side>>>(ei);        // #1
    scan_kernel<<<1, 1024, 0, s_side>>>();                        // #2
    scatter_kernel<<<(ET + 255) / 256, 256, 0, s_side>>>(ei);     // #3
    cudaEventRecord(ev_csr, s_side);

    // ---- layer 1 GEMM (main stream) ----                       // #4 (ncu)
    sgemm_fused_kernel<<<dim3(D1 / BN, (NN + BM - 1) / BM), 256>>>(
        x, W1, p_h1h, at_s1, at_d1, p_as1, p_ad1, NN, D1, IN1, H1);

    cudaStreamWaitEvent((cudaStream_t)0, ev_csr, 0);   // join CSR
    gat1_fused_kernel<<<(NN + 7) / 8, 256>>>(b1);                 // #5

    // ---- layer 2 ----
    sgemm_fused_kernel<<<dim3(C2 / BN, (NN + BM - 1) / BM), 256>>>(
        p_acc1, W2, p_h2h, at_s2, at_d2, p_as2, p_ad2, NN, C2, D1, 1);
    gat2_fused_kernel<<<(NN + 7) / 8, 256>>>(b2, out);
}

// round 16
// speedup vs baseline: 2.9917x; 1.1669x over previous
#include <cuda_runtime.h>
#include <cuda_fp16.h>
#include <math.h>

// Problem constants (fixed for this dataset)
#define NN 50000
#define EE 800000
#define ET (EE + NN)      // 850000 edges incl. self loops
#define H1 4
#define C1 64
#define D1 256            // H1*C1
#define C2 64
#define IN1 128
#define NEG_SLOPE 0.2f

// ---------------- scratch (device globals, no runtime alloc) ----------------
__device__ __half2 g_h1h[(size_t)NN * D1 / 2];   // fp16 h1 (gather source)
__device__ float   g_acc1[(size_t)NN * D1];      // layer1 output (post bias+relu)
__device__ float   g_as1[NN * H1];
__device__ float   g_ad1[NN * H1];
__device__ __half2 g_h2h[(size_t)NN * C2 / 2];
__device__ float   g_as2[NN];
__device__ float   g_ad2[NN];
// CSR by dst
__device__ int g_deg[NN];      // hist counters; reset by scatter for next call
__device__ int g_cur[NN];      // running write pointers (init by scan to row[d])
__device__ int g_row[NN + 1];
__device__ int g_srcs[ET];
__device__ int g_done;         // histscan completion counter
// per-edge softmax weights (written+read by the same warp in gat kernels)
__device__ float g_al1[(size_t)ET * H1];
__device__ float g_al2[ET];

__device__ __forceinline__ float lrelu(float v) {
    return v > 0.f ? v : NEG_SLOPE * v;
}

// online-softmax combine: (m,s) <- (m,s) ⊕ (om,os); NaN-safe for -inf pairs
__device__ __forceinline__ void osm_combine(float& m, float& s, float om, float os) {
    float nm = fmaxf(m, om);
    s = s * __expf(fmaxf(m - nm, -88.f)) + os * __expf(fmaxf(om - nm, -88.f));
    m = nm;
}

__device__ __forceinline__ unsigned f2tf32(float f) {
    unsigned r;
    asm("cvt.rna.tf32.f32 %0, %1;" : "=r"(r) : "f"(f));
    return r;
}

__device__ __forceinline__ unsigned smem_u32(const void* p) {
    return (unsigned)__cvta_generic_to_shared(p);
}

__device__ __forceinline__ void cp16(unsigned dst, const float* src, bool pred) {
    asm volatile("cp.async.cg.shared.global [%0], [%1], 16, %2;"
                 :: "r"(dst), "l"(src), "r"(pred ? 16 : 0));
}

// ---------------- CSR build: hist + (last block) scan ----------------
// 1024 threads/block. Histogram via atomics; the last block to finish runs
// the strip-mined coalesced exclusive scan (g_deg -> g_row, g_cur seeded).
__global__ void histscan_kernel(const int* __restrict__ ei) {
    int e = blockIdx.x * blockDim.x + threadIdx.x;
    if (e < ET) {
        int d = (e < EE) ? ei[EE + e] : (e - EE);
        atomicAdd(&g_deg[d], 1);
    }
    __threadfence();
    __syncthreads();
    __shared__ int is_last;
    if (threadIdx.x == 0)
        is_last = (atomicAdd(&g_done, 1) == (int)gridDim.x - 1) ? 1 : 0;
    __syncthreads();
    if (!is_last) return;

    // ---- scan (only the last block) ----
    __shared__ int wsum[32];
    int t = threadIdx.x, lane = t & 31, wid = t >> 5;
    int base = 0;
    for (int strip = 0; strip < NN; strip += 1024) {
        int idx = strip + t;
        int orig = (idx < NN) ? __ldcg(&g_deg[idx]) : 0;   // L2 (atomics) view
        int v = orig;
        #pragma unroll
        for (int o = 1; o < 32; o <<= 1) {
            int n = __shfl_up_sync(0xFFFFFFFFu, v, o);
            if (lane >= o) v += n;
        }
        if (lane == 31) wsum[wid] = v;
        __syncthreads();
        int w = wsum[lane];
        #pragma unroll
        for (int o = 1; o < 32; o <<= 1) {
            int n = __shfl_up_sync(0xFFFFFFFFu, w, o);
            if (lane >= o) w += n;
        }
        int wpre  = __shfl_sync(0xFFFFFFFFu, w, (wid + 31) & 31);
        if (wid == 0) wpre = 0;
        int total = __shfl_sync(0xFFFFFFFFu, w, 31);
        int excl = base + wpre + (v - orig);
        if (idx < NN) { g_row[idx] = excl; g_cur[idx] = excl; }
        base += total;
        __syncthreads();
    }
    if (t == 0) { g_row[NN] = base; g_done = 0; }
}

__global__ void scatter_kernel(const int* __restrict__ ei) {
    int e = blockIdx.x * blockDim.x + threadIdx.x;
    if (e < NN) g_deg[e] = 0;       // reset hist counters for the next call
    if (e >= ET) return;
    int s, d;
    if (e < EE) { s = ei[e]; d = ei[EE + e]; } else { s = d = e - EE; }
    int pos = atomicAdd(&g_cur[d], 1);
    g_srcs[pos] = s;
}

// ---------- tf32 tensor-core GEMM (cp.async pipeline) + fused epilogue ----
#define BM 128
#define BN 64
#define BK 16
#define APAD 20
#define BPAD 72

__global__ __launch_bounds__(256, 2)
void sgemm_fused_kernel(const float* __restrict__ A,
                        const float* __restrict__ B,
                        __half2* __restrict__ Ch,
                        const float* __restrict__ att_s,
                        const float* __restrict__ att_d,
                        float* __restrict__ as_out,
                        float* __restrict__ ad_out,
                        int M, int N, int K, int Hs) {
    __shared__ float A_sm[3][BM][APAD];
    __shared__ float B_sm[3][BK][BPAD];
    __shared__ float red_s[2][BM];
    __shared__ float red_d[2][BM];

    const int tid  = threadIdx.x;
    const int lane = tid & 31;
    const int wid  = tid >> 5;
    const int wm   = wid & 3;
    const int wn   = wid >> 2;
    const int g    = lane >> 2;
    const int t4   = lane & 3;
    const int row0 = blockIdx.y * BM, col0 = blockIdx.x * BN;

    const int am  = tid >> 2;
    const int ak  = (tid & 3) * 4;
    const int bkr = tid >> 4;
    const int bn4 = (tid & 15) * 4;

    const int nk = K / BK;

    const bool p0 = (row0 + am) < M;
    const bool p1 = (row0 + am + 64) < M;
    const float* ga0_base = A + (size_t)(p0 ? row0 + am      : 0) * K + ak;
    const float* ga1_base = A + (size_t)(p1 ? row0 + am + 64 : 0) * K + ak;
    const float* gb_base  = B + (size_t)bkr * N + col0 + bn4;

    #define ISSUE(kt, bufi) do {                                              \
        int k0i = (kt) * BK;                                                  \
        cp16(smem_u32(&A_sm[bufi][am][ak]),      ga0_base + k0i, p0);         \
        cp16(smem_u32(&A_sm[bufi][am + 64][ak]), ga1_base + k0i, p1);         \
        cp16(smem_u32(&B_sm[bufi][bkr][bn4]),    gb_base + (size_t)k0i * N, true); \
        asm volatile("cp.async.commit_group;");                               \
    } while (0)

    ISSUE(0, 0);
    if (nk > 1) ISSUE(1, 1);

    float acc[2][4][4] = {};
    for (int kt = 0; kt < nk; kt++) {
        if (kt + 1 < nk) asm volatile("cp.async.wait_group 1;");
        else             asm volatile("cp.async.wait_group 0;");
        __syncthreads();
        if (kt + 2 < nk) ISSUE(kt + 2, (kt + 2) % 3);
        const int buf = kt % 3;
        #pragma unroll
        for (int kc = 0; kc < 2; kc++) {
            const int k0 = kc * 8;
            unsigned af[2][4];
            #pragma unroll
            for (int mtl = 0; mtl < 2; mtl++) {
                int mb = wm * 32 + mtl * 16;
                af[mtl][0] = f2tf32(A_sm[buf][mb + g][k0 + t4]);
                af[mtl][1] = f2tf32(A_sm[buf][mb + 8 + g][k0 + t4]);
                af[mtl][2] = f2tf32(A_sm[buf][mb + g][k0 + t4 + 4]);
                af[mtl][3] = f2tf32(A_sm[buf][mb + 8 + g][k0 + t4 + 4]);
            }
            unsigned bf[4][2];
            #pragma unroll
            for (int ntl = 0; ntl < 4; ntl++) {
                int nb = wn * 32 + ntl * 8;
                bf[ntl][0] = f2tf32(B_sm[buf][k0 + t4][nb + g]);
                bf[ntl][1] = f2tf32(B_sm[buf][k0 + t4 + 4][nb + g]);
            }
            #pragma unroll
            for (int mtl = 0; mtl < 2; mtl++)
                #pragma unroll
                for (int ntl = 0; ntl < 4; ntl++)
                    asm volatile(
                        "mma.sync.aligned.m16n8k8.row.col.f32.tf32.tf32.f32 "
                        "{%0,%1,%2,%3}, {%4,%5,%6,%7}, {%8,%9}, {%0,%1,%2,%3};"
                        : "+f"(acc[mtl][ntl][0]), "+f"(acc[mtl][ntl][1]),
                          "+f"(acc[mtl][ntl][2]), "+f"(acc[mtl][ntl][3])
                        : "r"(af[mtl][0]), "r"(af[mtl][1]), "r"(af[mtl][2]), "r"(af[mtl][3]),
                          "r"(bf[ntl][0]), "r"(bf[ntl][1]));
        }
        __syncthreads();
    }
    #undef ISSUE

    float ps[2][2] = {}, pd[2][2] = {};
    #pragma unroll
    for (int mtl = 0; mtl < 2; mtl++) {
        int rlo = row0 + wm * 32 + mtl * 16 + g;
        int rhi = rlo + 8;
        #pragma unroll
        for (int ntl = 0; ntl < 4; ntl++) {
            int cn = wn * 32 + ntl * 8 + 2 * t4;
            float a0 = acc[mtl][ntl][0], a1 = acc[mtl][ntl][1];
            float a2 = acc[mtl][ntl][2], a3 = acc[mtl][ntl][3];
            if (rlo < M)
                Ch[((size_t)rlo * N + col0 + cn) / 2] = __floats2half2_rn(a0, a1);
            if (rhi < M)
                Ch[((size_t)rhi * N + col0 + cn) / 2] = __floats2half2_rn(a2, a3);
            float s0 = att_s[col0 + cn], s1 = att_s[col0 + cn + 1];
            float d0 = att_d[col0 + cn], d1 = att_d[col0 + cn + 1];
            ps[mtl][0] += a0 * s0 + a1 * s1;  pd[mtl][0] += a0 * d0 + a1 * d1;
            ps[mtl][1] += a2 * s0 + a3 * s1;  pd[mtl][1] += a2 * d0 + a3 * d1;
        }
        #pragma unroll
        for (int o = 1; o < 4; o <<= 1) {
            ps[mtl][0] += __shfl_xor_sync(0xFFFFFFFFu, ps[mtl][0], o);
            ps[mtl][1] += __shfl_xor_sync(0xFFFFFFFFu, ps[mtl][1], o);
            pd[mtl][0] += __shfl_xor_sync(0xFFFFFFFFu, pd[mtl][0], o);
            pd[mtl][1] += __shfl_xor_sync(0xFFFFFFFFu, pd[mtl][1], o);
        }
        if (t4 == 0) {
            int rloc = wm * 32 + mtl * 16 + g;
            red_s[wn][rloc]     = ps[mtl][0];
            red_s[wn][rloc + 8] = ps[mtl][1];
            red_d[wn][rloc]     = pd[mtl][0];
            red_d[wn][rloc + 8] = pd[mtl][1];
        }
    }
    __syncthreads();
    if (tid < BM) {
        int r = row0 + tid;
        if (r < M) {
            as_out[r * Hs + blockIdx.x] = red_s[0][tid] + red_s[1][tid];
            ad_out[r * Hs + blockIdx.x] = red_d[0][tid] + red_d[1][tid];
        }
    }
}

// ---------------- fused layer1 ----------------
// one warp per dst node. Pass A: online softmax. Pass B: write per-edge
// alphas (coalesced). Pass C: gather with only ONE dependent load per edge.
__global__ void gat1_fused_kernel(const float* __restrict__ b1) {
    int w = (blockIdx.x * blockDim.x + threadIdx.x) >> 5;
    int lane = threadIdx.x & 31;
    if (w >= NN) return;
    int beg = g_row[w], end = g_row[w + 1];

    float4 adv = *reinterpret_cast<const float4*>(g_ad1 + w * H1);

    // pass A: online softmax (per-lane running max + rescaled sum)
    float4 mx = make_float4(-INFINITY, -INFINITY, -INFINITY, -INFINITY);
    float4 sm = make_float4(0.f, 0.f, 0.f, 0.f);
    for (int i = beg + lane; i < end; i += 32) {
        int s = g_srcs[i];
        float4 a = *reinterpret_cast<const float4*>(g_as1 + s * H1);
        float vx = lrelu(a.x + adv.x), vy = lrelu(a.y + adv.y);
        float vz = lrelu(a.z + adv.z), vw = lrelu(a.w + adv.w);
        float nx = fmaxf(mx.x, vx), ny = fmaxf(mx.y, vy);
        float nz = fmaxf(mx.z, vz), nw = fmaxf(mx.w, vw);
        sm.x = sm.x * __expf(mx.x - nx) + __expf(vx - nx);
        sm.y = sm.y * __expf(mx.y - ny) + __expf(vy - ny);
        sm.z = sm.z * __expf(mx.z - nz) + __expf(vz - nz);
        sm.w = sm.w * __expf(mx.w - nw) + __expf(vw - nw);
        mx.x = nx; mx.y = ny; mx.z = nz; mx.w = nw;
    }
    #pragma unroll
    for (int o = 1; o < 32; o <<= 1) {
        float omx, osx;
        omx = __shfl_xor_sync(0xFFFFFFFFu, mx.x, o);
        osx = __shfl_xor_sync(0xFFFFFFFFu, sm.x, o);
        osm_combine(mx.x, sm.x, omx, osx);
        omx = __shfl_xor_sync(0xFFFFFFFFu, mx.y, o);
        osx = __shfl_xor_sync(0xFFFFFFFFu, sm.y, o);
        osm_combine(mx.y, sm.y, omx, osx);
        omx = __shfl_xor_sync(0xFFFFFFFFu, mx.z, o);
        osx = __shfl_xor_sync(0xFFFFFFFFu, sm.z, o);
        osm_combine(mx.z, sm.z, omx, osx);
        omx = __shfl_xor_sync(0xFFFFFFFFu, mx.w, o);
        osx = __shfl_xor_sync(0xFFFFFFFFu, sm.w, o);
        osm_combine(mx.w, sm.w, omx, osx);
    }
    float4 inv = make_float4(1.f / (sm.x + 1e-16f), 1.f / (sm.y + 1e-16f),
                             1.f / (sm.z + 1e-16f), 1.f / (sm.w + 1e-16f));

    // pass B: write per-edge alphas (float4 per edge, coalesced across lanes)
    for (int i = beg + lane; i < end; i += 32) {
        int s = g_srcs[i];
        float4 a = *reinterpret_cast<const float4*>(g_as1 + s * H1);
        float4 al;
        al.x = __expf(lrelu(a.x + adv.x) - mx.x) * inv.x;
        al.y = __expf(lrelu(a.y + adv.y) - mx.y) * inv.y;
        al.z = __expf(lrelu(a.z + adv.z) - mx.z) * inv.z;
        al.w = __expf(lrelu(a.w + adv.w) - mx.w) * inv.w;
        *reinterpret_cast<float4*>(&g_al1[(size_t)i * H1]) = al;
    }
    __syncwarp();

    int head = lane >> 3;

    // pass C: sequential srcs/alpha reads + one dependent gather per edge
    float acc[8] = {};
    #pragma unroll 4
    for (int i = beg; i < end; i++) {
        int s = g_srcs[i];                              // broadcast, sequential
        float alpha = g_al1[(size_t)i * H1 + head];     // sequential
        const uint4* hp = reinterpret_cast<const uint4*>(g_h1h + (size_t)s * (D1 / 2));
        uint4 u = hp[lane];
        float2 f0 = __half22float2(*reinterpret_cast<__half2*>(&u.x));
        float2 f1 = __half22float2(*reinterpret_cast<__half2*>(&u.y));
        float2 f2 = __half22float2(*reinterpret_cast<__half2*>(&u.z));
        float2 f3 = __half22float2(*reinterpret_cast<__half2*>(&u.w));
        acc[0] += f0.x * alpha; acc[1] += f0.y * alpha;
        acc[2] += f1.x * alpha; acc[3] += f1.y * alpha;
        acc[4] += f2.x * alpha; acc[5] += f2.y * alpha;
        acc[6] += f3.x * alpha; acc[7] += f3.y * alpha;
    }

    int cb = lane * 8;
    float* op = g_acc1 + (size_t)w * D1 + cb;
    #pragma unroll
    for (int j = 0; j < 8; j++) {
        float v = acc[j] + b1[cb + j];
        op[j] = v > 0.f ? v : 0.f;
    }
}

// ---------------- fused layer2 ----------------
__global__ void gat2_fused_kernel(const float* __restrict__ b2,
                                  float* __restrict__ out) {
    int w = (blockIdx.x * blockDim.x + threadIdx.x) >> 5;
    int lane = threadIdx.x & 31;
    if (w >= NN) return;
    int beg = g_row[w], end = g_row[w + 1];

    float ad = g_ad2[w];

    float mxv = -INFINITY, smv = 0.f;
    for (int i = beg + lane; i < end; i += 32) {
        int s = g_srcs[i];
        float v = lrelu(g_as2[s] + ad);
        float nm = fmaxf(mxv, v);
        smv = smv * __expf(mxv - nm) + __expf(v - nm);
        mxv = nm;
    }
    #pragma unroll
    for (int o = 1; o < 32; o <<= 1) {
        float om = __shfl_xor_sync(0xFFFFFFFFu, mxv, o);
        float os = __shfl_xor_sync(0xFFFFFFFFu, smv, o);
        osm_combine(mxv, smv, om, os);
    }
    float inv = 1.f / (smv + 1e-16f);

    for (int i = beg + lane; i < end; i += 32) {
        int s = g_srcs[i];
        g_al2[i] = __expf(lrelu(g_as2[s] + ad) - mxv) * inv;
    }
    __syncwarp();

    float a0 = 0.f, a1 = 0.f;
    #pragma unroll 4
    for (int i = beg; i < end; i++) {
        int s = g_srcs[i];
        float alpha = g_al2[i];
        __half2 hv = g_h2h[(size_t)s * (C2 / 2) + lane];
        float2 v = __half22float2(hv);
        a0 += v.x * alpha;
        a1 += v.y * alpha;
    }
    float* op = out + (size_t)w * C2 + 2 * lane;
    op[0] = a0 + b2[2 * lane];
    op[1] = a1 + b2[2 * lane + 1];
}

extern "C" void kernel_launch(void* const* d_in, const int* in_sizes, int n_in,
                              void* d_out, int out_size) {
    const float* x     = (const float*)d_in[0];
    const int*   ei    = (const int*)d_in[1];     // int32
    const float* W1    = (const float*)d_in[2];
    const float* at_s1 = (const float*)d_in[3];
    const float* at_d1 = (const float*)d_in[4];
    const float* b1    = (const float*)d_in[5];
    const float* W2    = (const float*)d_in[6];
    const float* at_s2 = (const float*)d_in[7];
    const float* at_d2 = (const float*)d_in[8];
    const float* b2    = (const float*)d_in[9];
    float* out = (float*)d_out;

    static float*   p_acc1 = nullptr;
    static __half2* p_h1h  = nullptr;
    static __half2* p_h2h  = nullptr;
    static float *p_as1, *p_ad1, *p_as2, *p_ad2;
    static cudaStream_t s_side = nullptr;
    static cudaEvent_t  ev_root = nullptr, ev_csr = nullptr;
    if (!p_acc1) {   // address lookup + stream/event creation (first call is
                     // the un-captured correctness run; no device mem alloc)
        cudaGetSymbolAddress((void**)&p_acc1, g_acc1);
        cudaGetSymbolAddress((void**)&p_h1h, g_h1h);
        cudaGetSymbolAddress((void**)&p_h2h, g_h2h);
        cudaGetSymbolAddress((void**)&p_as1, g_as1);
        cudaGetSymbolAddress((void**)&p_ad1, g_ad1);
        cudaGetSymbolAddress((void**)&p_as2, g_as2);
        cudaGetSymbolAddress((void**)&p_ad2, g_ad2);
        cudaStreamCreateWithFlags(&s_side, cudaStreamNonBlocking);
        cudaEventCreateWithFlags(&ev_root, cudaEventDisableTiming);
        cudaEventCreateWithFlags(&ev_csr, cudaEventDisableTiming);
    }

    // ---- fork: CSR build on side stream, overlapped with layer-1 GEMM ----
    cudaEventRecord(ev_root, (cudaStream_t)0);
    cudaStreamWaitEvent(s_side, ev_root, 0);
    histscan_kernel<<<(ET + 1023) / 1024, 1024, 0, s_side>>>(ei); // #1
    scatter_kernel<<<(ET + 255) / 256, 256, 0, s_side>>>(ei);     // #2
    cudaEventRecord(ev_csr, s_side);

    // ---- layer 1 GEMM (main stream) ----                       // #3
    sgemm_fused_kernel<<<dim3(D1 / BN, (NN + BM - 1) / BM), 256>>>(
        x, W1, p_h1h, at_s1, at_d1, p_as1, p_ad1, NN, D1, IN1, H1);

    cudaStreamWaitEvent((cudaStream_t)0, ev_csr, 0);   // join CSR
    gat1_fused_kernel<<<(NN + 7) / 8, 256>>>(b1);                 // #4 (ncu)

    // ---- layer 2 ----
    sgemm_fused_kernel<<<dim3(C2 / BN, (NN + BM - 1) / BM), 256>>>(
        p_acc1, W2, p_h2h, at_s2, at_d2, p_as2, p_ad2, NN, C2, D1, 1);
    gat2_fused_kernel<<<(NN + 7) / 8, 256>>>(b2, out);
}